// round 12
// baseline (speedup 1.0000x reference)
#include <cuda_runtime.h>
#include <cuda_fp16.h>
#include <stdint.h>
#include <math.h>

#define S_LEN 2048
#define H_DIM 1024
#define NHEAD 16
#define HEADD 64
#define INNER_DIM 4096

// ---------------- scratch ----------------
__device__ float  g_qkv[S_LEN * 3 * H_DIM];
__device__ float  g_hid2[S_LEN * H_DIM];
__device__ float  g_hid3[S_LEN * H_DIM];
__device__ float  g_q[S_LEN * H_DIM];
__device__ float  g_kv[S_LEN * 2 * H_DIM];
__device__ __half g_wh[33554432];     // weight hi/lo planes
__device__ __half g_fh[12582912];     // per-head Q/K/V hi+lo planes
__device__ __half g_xh[2097152], g_xl[2097152];      // LN output planes
__device__ __half g_eh[2097152], g_el[2097152];      // encoder planes
__device__ __half g_ath[2097152], g_atl[2097152];    // attention output planes
__device__ __half g_mh[8388608],  g_ml[8388608];     // MLP inner planes

#define WH_CA  0
#define WH_AP  6291456
#define WH_QA  8388608
#define WH_XKV 10485760
#define WH_XP  14680064
#define WH_FC  16777216
#define WH_MP  25165824
#define SZ_CA  3145728
#define SZ_AP  1048576
#define SZ_QA  1048576
#define SZ_XKV 2097152
#define SZ_XP  1048576
#define SZ_FC  4194304
#define SZ_MP  4194304
#define FH_PL  2097152

#define SM_STRIDE 40                  // 32 data + 8 pad halves
#define PL_H (128 * SM_STRIDE)        // one plane tile in halves (5120)
#define STG_H (4 * PL_H)              // stage = A(2 planes)+B(2 planes) halves
#define DSMEM (2 * STG_H * 2)         // bytes, 2 stages = 81920

__device__ __forceinline__ float gelu_new(float x) {
    const float c = 0.7978845608028654f;
    return 0.5f * x * (1.0f + tanhf(c * (x + 0.044715f * x * x * x)));
}
__device__ __forceinline__ uint32_t smem_u32(const void* p) {
    uint32_t a;
    asm("{ .reg .u64 t; cvta.to.shared.u64 t, %1; cvt.u32.u64 %0, t; }" : "=r"(a) : "l"(p));
    return a;
}
__device__ __forceinline__ void mma_16816(float c[4], const uint32_t a[4], const uint32_t b[2]) {
    asm volatile("mma.sync.aligned.m16n8k16.row.col.f32.f16.f16.f32 "
        "{%0,%1,%2,%3}, {%4,%5,%6,%7}, {%8,%9}, {%0,%1,%2,%3};"
        : "+f"(c[0]), "+f"(c[1]), "+f"(c[2]), "+f"(c[3])
        : "r"(a[0]), "r"(a[1]), "r"(a[2]), "r"(a[3]), "r"(b[0]), "r"(b[1]));
}
__device__ __forceinline__ void ldm_x4(uint32_t r[4], uint32_t addr) {
    asm volatile("ldmatrix.sync.aligned.m8n8.x4.shared.b16 {%0,%1,%2,%3}, [%4];"
        : "=r"(r[0]), "=r"(r[1]), "=r"(r[2]), "=r"(r[3]) : "r"(addr));
}
__device__ __forceinline__ void ldm_x4_t(uint32_t r[4], uint32_t addr) {
    asm volatile("ldmatrix.sync.aligned.m8n8.x4.trans.shared.b16 {%0,%1,%2,%3}, [%4];"
        : "=r"(r[0]), "=r"(r[1]), "=r"(r[2]), "=r"(r[3]) : "r"(addr));
}
__device__ __forceinline__ void cp16(uint32_t d, const void* s) {
    asm volatile("cp.async.cg.shared.global [%0], [%1], 16;" :: "r"(d), "l"(s));
}
#define CP_COMMIT() asm volatile("cp.async.commit_group;" ::: "memory")
#define CP_WAIT1()  asm volatile("cp.async.wait_group 1;" ::: "memory")
#define CP_WAIT0()  asm volatile("cp.async.wait_group 0;" ::: "memory")

// ================= dense plane x plane GEMM ================================
// C[M,N] = A[M,K] @ B^T. A,B as fp16 hi/lo planes ([M][K] / [N][K]).
// 128x128 tile, BK=32, 2-stage cp.async double buffer, 3 MMA combos.
__global__ void __launch_bounds__(256) pl_gemm(
    const __half* __restrict__ Ah, const __half* __restrict__ Al, int lda,
    const __half* __restrict__ Bh, const __half* __restrict__ Bl, int ldb,
    const float* __restrict__ bias, const float* __restrict__ res, int ldres,
    float* C, __half* Ch, __half* Cl, int ldc, int K, int act)
{
    extern __shared__ __half dsm[];
    uint32_t sb = smem_u32(dsm);

    int t = threadIdx.x, w = t >> 5, lane = t & 31;
    int warpY = w & 1, warpX = w >> 1;
    int wm0 = warpY * 64, wn0 = warpX * 32;
    int m0 = blockIdx.y * 128, n0 = blockIdx.x * 128;

    // cp.async task mapping: 4 A-subtasks + 4 B-subtasks per thread
    int id0 = t * 4;
    int apl = id0 >> 9, arem = id0 & 511;
    int arow = arem >> 2, aseg0 = arem & 3;   // 4 consecutive segs when aseg0==0? no: id0..id0+3 vary seg
    // note: t*4 → tasks t*4+i have same (pl,row) iff (t*4 & 3)==0, true since id0%4==0
    const __half* Apl = apl ? Al : Ah;
    const __half* Bpl = apl ? Bl : Bh;
    uint32_t aDst0 = sb + (uint32_t)(apl * PL_H + arow * SM_STRIDE) * 2;
    uint32_t bDst0 = sb + (uint32_t)(2 * PL_H + apl * PL_H + arow * SM_STRIDE) * 2;

    int loff = ((lane & 7) + ((lane >> 3) & 1) * 8) * SM_STRIDE + (lane >> 4) * 8;
    uint32_t aBase = sb + (uint32_t)(wm0 * SM_STRIDE + loff) * 2;
    uint32_t bBase = sb + (uint32_t)(2 * PL_H + wn0 * SM_STRIDE + loff) * 2;

    float acc[4][4][4] = {};
    int nch = K >> 5;

    // issue chunk 0 into stage 0
    {
        const __half* ga = Apl + (long long)(m0 + arow) * lda;
        const __half* gb = Bpl + (long long)(n0 + arow) * ldb;
#pragma unroll
        for (int i = 0; i < 4; i++) {
            cp16(aDst0 + i * 16, ga + i * 8);
            cp16(bDst0 + i * 16, gb + i * 8);
        }
    }
    CP_COMMIT();

    for (int c = 0; c < nch; c++) {
        int st = c & 1;
        if (c + 1 < nch) {
            int k0 = (c + 1) << 5;
            uint32_t so = (uint32_t)(((c + 1) & 1) * STG_H) * 2;
            const __half* ga = Apl + (long long)(m0 + arow) * lda + k0;
            const __half* gb = Bpl + (long long)(n0 + arow) * ldb + k0;
#pragma unroll
            for (int i = 0; i < 4; i++) {
                cp16(aDst0 + so + i * 16, ga + i * 8);
                cp16(bDst0 + so + i * 16, gb + i * 8);
            }
            CP_COMMIT();
            CP_WAIT1();
        } else {
            CP_WAIT0();
        }
        __syncthreads();

        uint32_t so = (uint32_t)(st * STG_H) * 2;
        uint32_t aH = aBase + so, aL = aH + PL_H * 2;
        uint32_t bH = bBase + so, bL = bH + PL_H * 2;
#pragma unroll
        for (int kk = 0; kk < 32; kk += 16) {
            uint32_t a[4][4], bq[2][4];
#pragma unroll
            for (int i = 0; i < 4; i++) ldm_x4(a[i], aH + (i * 16 * SM_STRIDE + kk) * 2);
            ldm_x4(bq[0], bH + kk * 2);
            ldm_x4(bq[1], bH + (16 * SM_STRIDE + kk) * 2);
#pragma unroll
            for (int i = 0; i < 4; i++)
#pragma unroll
                for (int j = 0; j < 4; j++) {
                    uint32_t bf[2] = { bq[j >> 1][j & 1], bq[j >> 1][2 + (j & 1)] };
                    mma_16816(acc[i][j], a[i], bf);
                }
            {   // A-hi x B-lo
                uint32_t blq[2][4];
                ldm_x4(blq[0], bL + kk * 2);
                ldm_x4(blq[1], bL + (16 * SM_STRIDE + kk) * 2);
#pragma unroll
                for (int i = 0; i < 4; i++)
#pragma unroll
                    for (int j = 0; j < 4; j++) {
                        uint32_t bf[2] = { blq[j >> 1][j & 1], blq[j >> 1][2 + (j & 1)] };
                        mma_16816(acc[i][j], a[i], bf);
                    }
            }
            {   // A-lo x B-hi
                uint32_t al[4][4];
#pragma unroll
                for (int i = 0; i < 4; i++) ldm_x4(al[i], aL + (i * 16 * SM_STRIDE + kk) * 2);
#pragma unroll
                for (int i = 0; i < 4; i++)
#pragma unroll
                    for (int j = 0; j < 4; j++) {
                        uint32_t bf[2] = { bq[j >> 1][j & 1], bq[j >> 1][2 + (j & 1)] };
                        mma_16816(acc[i][j], al[i], bf);
                    }
            }
        }
        __syncthreads();
    }

    int rb = m0 + wm0 + (lane >> 2);
    int cb = n0 + wn0 + ((lane & 3) << 1);
#pragma unroll
    for (int i = 0; i < 4; i++) {
#pragma unroll
        for (int j = 0; j < 4; j++) {
            int cc = cb + j * 8;
            float b0 = bias ? bias[cc] : 0.f, b1 = bias ? bias[cc + 1] : 0.f;
#pragma unroll
            for (int h = 0; h < 2; h++) {
                int r = rb + i * 16 + h * 8;
                float v0 = acc[i][j][2 * h] + b0;
                float v1 = acc[i][j][2 * h + 1] + b1;
                if (act) { v0 = gelu_new(v0); v1 = gelu_new(v1); }
                if (Ch) {
                    __half h0 = __float2half_rn(v0), h1 = __float2half_rn(v1);
                    __half l0 = __float2half_rn(v0 - __half2float(h0));
                    __half l1 = __float2half_rn(v1 - __half2float(h1));
                    long long o = (long long)r * ldc + cc;
                    *(__half2*)&Ch[o] = __halves2half2(h0, h1);
                    *(__half2*)&Cl[o] = __halves2half2(l0, l1);
                } else {
                    if (res) {
                        const float* rp = res + (long long)r * ldres + cc;
                        v0 += rp[0]; v1 += rp[1];
                    }
                    *(float2*)&C[(long long)r * ldc + cc] = make_float2(v0, v1);
                }
            }
        }
    }
}

// ================= fused flash attention (outputs fp16 hi/lo planes) =======
__global__ void __launch_bounds__(256) flash_attn(
    const __half* __restrict__ QH, const __half* __restrict__ QL,
    const __half* __restrict__ KH, const __half* __restrict__ KL,
    const __half* __restrict__ VH, const __half* __restrict__ VL,
    const float* __restrict__ kbias,
    __half* __restrict__ OH, __half* __restrict__ OL, int mode)
{
    constexpr int ST = 72;
    constexpr int PL = 128 * ST;
    extern __shared__ __half sm[];
    __half* sQh = sm;
    __half* sKh = sm + 2 * PL;
    __half* sVh = sm + 4 * PL;

    int t = threadIdx.x, w = t >> 5, lane = t & 31;
    int qt = gridDim.x - 1 - blockIdx.x;
    int h = blockIdx.y;
    int m0 = qt * 128;
    size_t hb = (size_t)h * S_LEN * 64;

    {
        int row = t >> 1, seg = (t & 1) * 32;
        size_t g = hb + (size_t)(m0 + row) * 64 + seg;
        uint4* dh = (uint4*)(sQh + row * ST + seg);
        uint4* dl = (uint4*)(sQh + PL + row * ST + seg);
#pragma unroll
        for (int u = 0; u < 4; u++) {
            dh[u] = ((const uint4*)(QH + g))[u];
            dl[u] = ((const uint4*)(QL + g))[u];
        }
    }

    int wr = w * 16;
    int krow = (lane & 7) + ((lane >> 3) & 1) * 8;
    int chi = (lane >> 4) * 8;
    uint32_t aQh = smem_u32(sQh) + ((wr + krow) * ST + chi) * 2;
    uint32_t aK = smem_u32(sKh) + (krow * ST + chi) * 2;
    uint32_t aV = smem_u32(sVh) + (krow * ST + chi) * 2;

    float mrow0 = -1e30f, mrow1 = -1e30f, l0 = 0.f, l1 = 0.f;
    float o[8][4] = {};
    int r_lo = m0 + wr + (lane >> 2);
    int cbase = 2 * (lane & 3);

    int nkb = (mode == 0) ? (qt + 1) : min(16, qt + 2);
    for (int kb = 0; kb < nkb; kb++) {
        __syncthreads();
        {
            int row = t >> 1, seg = (t & 1) * 32;
            size_t g = hb + (size_t)(kb * 128 + row) * 64 + seg;
            uint4* d0 = (uint4*)(sKh + row * ST + seg);
            uint4* d1 = (uint4*)(sKh + PL + row * ST + seg);
            uint4* d2 = (uint4*)(sVh + row * ST + seg);
            uint4* d3 = (uint4*)(sVh + PL + row * ST + seg);
#pragma unroll
            for (int u = 0; u < 4; u++) {
                d0[u] = ((const uint4*)(KH + g))[u];
                d1[u] = ((const uint4*)(KL + g))[u];
                d2[u] = ((const uint4*)(VH + g))[u];
                d3[u] = ((const uint4*)(VL + g))[u];
            }
        }
        __syncthreads();

        float s[16][4] = {};
#pragma unroll
        for (int kk = 0; kk < 64; kk += 16) {
            uint32_t ah[4], al[4];
            ldm_x4(ah, aQh + kk * 2);
            ldm_x4(al, aQh + PL * 2 + kk * 2);
#pragma unroll
            for (int nb = 0; nb < 8; nb++) {
                uint32_t bh[4], bl[4];
                uint32_t off = (uint32_t)(nb * 16 * ST + kk) * 2;
                ldm_x4(bh, aK + off);
                ldm_x4(bl, aK + PL * 2 + off);
#pragma unroll
                for (int j = 0; j < 2; j++) {
                    uint32_t bfh[2] = { bh[j], bh[2 + j] };
                    uint32_t bfl[2] = { bl[j], bl[2 + j] };
                    mma_16816(s[nb * 2 + j], ah, bfh);
                    mma_16816(s[nb * 2 + j], ah, bfl);
                    mma_16816(s[nb * 2 + j], al, bfh);
                }
            }
        }

        int k0c = kb * 128;
        float mx0 = mrow0, mx1 = mrow1;
        int lim0 = (mode == 0) ? r_lo : r_lo + 2;
        int lim1 = lim0 + 8;
#pragma unroll
        for (int nf = 0; nf < 16; nf++) {
            int c0 = k0c + nf * 8 + cbase;
            float b0 = (mode == 1) ? kbias[c0] : 0.f;
            float b1 = (mode == 1) ? kbias[c0 + 1] : 0.f;
            s[nf][0] = (c0 <= lim0)     ? s[nf][0] * 0.125f + b0 : -1e30f;
            s[nf][1] = (c0 + 1 <= lim0) ? s[nf][1] * 0.125f + b1 : -1e30f;
            s[nf][2] = (c0 <= lim1)     ? s[nf][2] * 0.125f + b0 : -1e30f;
            s[nf][3] = (c0 + 1 <= lim1) ? s[nf][3] * 0.125f + b1 : -1e30f;
            mx0 = fmaxf(mx0, fmaxf(s[nf][0], s[nf][1]));
            mx1 = fmaxf(mx1, fmaxf(s[nf][2], s[nf][3]));
        }
        mx0 = fmaxf(mx0, __shfl_xor_sync(0xffffffffu, mx0, 1));
        mx0 = fmaxf(mx0, __shfl_xor_sync(0xffffffffu, mx0, 2));
        mx1 = fmaxf(mx1, __shfl_xor_sync(0xffffffffu, mx1, 1));
        mx1 = fmaxf(mx1, __shfl_xor_sync(0xffffffffu, mx1, 2));
        float corr0 = __expf(mrow0 - mx0), corr1 = __expf(mrow1 - mx1);
        mrow0 = mx0; mrow1 = mx1;

        float sum0 = 0.f, sum1 = 0.f;
        uint32_t p[16][2];
#pragma unroll
        for (int nf = 0; nf < 16; nf++) {
            float p0 = __expf(s[nf][0] - mx0), p1 = __expf(s[nf][1] - mx0);
            float p2 = __expf(s[nf][2] - mx1), p3 = __expf(s[nf][3] - mx1);
            sum0 += p0 + p1; sum1 += p2 + p3;
            __half2 h01 = __float22half2_rn(make_float2(p0, p1));
            __half2 h23 = __float22half2_rn(make_float2(p2, p3));
            p[nf][0] = *(uint32_t*)&h01;
            p[nf][1] = *(uint32_t*)&h23;
        }
        sum0 += __shfl_xor_sync(0xffffffffu, sum0, 1);
        sum0 += __shfl_xor_sync(0xffffffffu, sum0, 2);
        sum1 += __shfl_xor_sync(0xffffffffu, sum1, 1);
        sum1 += __shfl_xor_sync(0xffffffffu, sum1, 2);
        l0 = l0 * corr0 + sum0;
        l1 = l1 * corr1 + sum1;
#pragma unroll
        for (int df = 0; df < 8; df++) {
            o[df][0] *= corr0; o[df][1] *= corr0;
            o[df][2] *= corr1; o[df][3] *= corr1;
        }

#pragma unroll
        for (int kc = 0; kc < 8; kc++) {
            uint32_t a[4] = { p[2 * kc][0], p[2 * kc][1], p[2 * kc + 1][0], p[2 * kc + 1][1] };
#pragma unroll
            for (int dx = 0; dx < 4; dx++) {
                uint32_t bh[4], bl[4];
                uint32_t off = (uint32_t)(kc * 16 * ST + dx * 16) * 2;
                ldm_x4_t(bh, aV + off);
                ldm_x4_t(bl, aV + PL * 2 + off);
                uint32_t bf0[2] = { bh[0], bh[1] }, bf1[2] = { bh[2], bh[3] };
                uint32_t bg0[2] = { bl[0], bl[1] }, bg1[2] = { bl[2], bl[3] };
                mma_16816(o[dx * 2],     a, bf0);
                mma_16816(o[dx * 2 + 1], a, bf1);
                mma_16816(o[dx * 2],     a, bg0);
                mma_16816(o[dx * 2 + 1], a, bg1);
            }
        }
    }

    float inv0 = 1.f / l0, inv1 = 1.f / l1;
    int colb = h * 64 + cbase;
#pragma unroll
    for (int df = 0; df < 8; df++) {
        int cc = colb + df * 8;
        float v0 = o[df][0] * inv0, v1 = o[df][1] * inv0;
        float v2 = o[df][2] * inv1, v3 = o[df][3] * inv1;
        __half h0 = __float2half_rn(v0), h1 = __float2half_rn(v1);
        __half h2 = __float2half_rn(v2), h3 = __float2half_rn(v3);
        long long o0 = (long long)r_lo * H_DIM + cc;
        long long o1 = (long long)(r_lo + 8) * H_DIM + cc;
        *(__half2*)&OH[o0] = __halves2half2(h0, h1);
        *(__half2*)&OL[o0] = __halves2half2(__float2half_rn(v0 - __half2float(h0)),
                                            __float2half_rn(v1 - __half2float(h1)));
        *(__half2*)&OH[o1] = __halves2half2(h2, h3);
        *(__half2*)&OL[o1] = __halves2half2(__float2half_rn(v2 - __half2float(h2)),
                                            __float2half_rn(v3 - __half2float(h3)));
    }
}

// split fp32 [s][ld] cols coloff.. into per-head planes [h][s][64]
__global__ void split_hilo(const float* __restrict__ src, int ld, int coloff,
                           __half* __restrict__ hi, __half* __restrict__ lo)
{
    int s = blockIdx.x, t = threadIdx.x;
#pragma unroll
    for (int i = 0; i < 4; i++) {
        int c = t + i * 256;
        float v = src[(long long)s * ld + coloff + c];
        int hh = c >> 6, d = c & 63;
        __half hv = __float2half_rn(v);
        size_t o = ((size_t)hh * S_LEN + s) * 64 + d;
        hi[o] = hv;
        lo[o] = __float2half_rn(v - __half2float(hv));
    }
}

// split fp32 [s][1024] into row-major planes
__global__ void split_plane(const float* __restrict__ src,
                            __half* __restrict__ hi, __half* __restrict__ lo)
{
    int s = blockIdx.x, t = threadIdx.x;
#pragma unroll
    for (int i = 0; i < 4; i++) {
        int c = t + i * 256;
        float v = src[(long long)s * H_DIM + c];
        __half hv = __float2half_rn(v);
        long long o = (long long)s * H_DIM + c;
        hi[o] = hv;
        lo[o] = __float2half_rn(v - __half2float(hv));
    }
}

// LayerNorm emitting fp16 hi/lo planes
__global__ void ln_plane(const float* __restrict__ X, const float* __restrict__ g,
                         const float* __restrict__ b,
                         __half* __restrict__ YH, __half* __restrict__ YL)
{
    const float* x = X + (long long)blockIdx.x * H_DIM;
    long long yo = (long long)blockIdx.x * H_DIM;
    int tid = threadIdx.x;
    float v[4], s = 0.f, ss = 0.f;
#pragma unroll
    for (int i = 0; i < 4; i++) { v[i] = x[tid + i * 256]; s += v[i]; ss += v[i] * v[i]; }
    __shared__ float r1[256], r2[256];
    r1[tid] = s; r2[tid] = ss;
    __syncthreads();
#pragma unroll
    for (int st = 128; st >= 1; st >>= 1) {
        if (tid < st) { r1[tid] += r1[tid + st]; r2[tid] += r2[tid + st]; }
        __syncthreads();
    }
    float mean = r1[0] * (1.0f / H_DIM);
    float inv = rsqrtf(r2[0] * (1.0f / H_DIM) - mean * mean + 1e-5f);
#pragma unroll
    for (int i = 0; i < 4; i++) {
        int c = tid + i * 256;
        float y = (v[i] - mean) * inv * g[c] + b[c];
        __half h = __float2half_rn(y);
        YH[yo + c] = h;
        YL[yo + c] = __float2half_rn(y - __half2float(h));
    }
}

// transpose fp32 [r][c] -> fp16 hi/lo planes [c][r]  (weights)
__global__ void transpose_hilo(const float* __restrict__ in, int ldi,
                               __half* __restrict__ hi, __half* __restrict__ lo, int ldo)
{
    __shared__ float tbuf[32][33];
    int r0 = blockIdx.y * 32, c0 = blockIdx.x * 32;
    int tx = threadIdx.x, ty = threadIdx.y;
#pragma unroll
    for (int i = 0; i < 4; i++)
        tbuf[ty + i * 8][tx] = in[(long long)(r0 + ty + i * 8) * ldi + c0 + tx];
    __syncthreads();
#pragma unroll
    for (int i = 0; i < 4; i++) {
        float v = tbuf[tx][ty + i * 8];
        __half h = __float2half_rn(v);
        long long o = (long long)(c0 + ty + i * 8) * ldo + r0 + tx;
        hi[o] = h;
        lo[o] = __float2half_rn(v - __half2float(h));
    }
}

// ---------------------------------------------------------------------------
extern "C" void kernel_launch(void* const* d_in, const int* in_sizes, int n_in,
                              void* d_out, int out_size)
{
    const float* hidden = (const float*)d_in[0];
    const float* enc    = (const float*)d_in[1];
    const float* scorer = (const float*)d_in[2];
    const float* ln1_g = (const float*)d_in[3],  *ln1_b = (const float*)d_in[4];
    const float* c_attn_w = (const float*)d_in[5], *c_attn_b = (const float*)d_in[6];
    const float* attn_proj_w = (const float*)d_in[7], *attn_proj_b = (const float*)d_in[8];
    const float* lnx_g = (const float*)d_in[9],  *lnx_b = (const float*)d_in[10];
    const float* q_attn_w = (const float*)d_in[11], *q_attn_b = (const float*)d_in[12];
    const float* x_kv_w = (const float*)d_in[13], *x_kv_b = (const float*)d_in[14];
    const float* x_proj_w = (const float*)d_in[15], *x_proj_b = (const float*)d_in[16];
    const float* ln2_g = (const float*)d_in[17], *ln2_b = (const float*)d_in[18];
    const float* fc_w = (const float*)d_in[19], *fc_b = (const float*)d_in[20];
    const float* mlp_proj_w = (const float*)d_in[21], *mlp_proj_b = (const float*)d_in[22];
    float* out = (float*)d_out;

    float *qkv, *hid2, *hid3, *qb, *kv;
    __half *wh, *fh, *xh, *xl, *eh, *el, *ath, *atl, *mh, *ml;
    cudaGetSymbolAddress((void**)&qkv, g_qkv);
    cudaGetSymbolAddress((void**)&hid2, g_hid2);
    cudaGetSymbolAddress((void**)&hid3, g_hid3);
    cudaGetSymbolAddress((void**)&qb, g_q);
    cudaGetSymbolAddress((void**)&kv, g_kv);
    cudaGetSymbolAddress((void**)&wh, g_wh);
    cudaGetSymbolAddress((void**)&fh, g_fh);
    cudaGetSymbolAddress((void**)&xh, g_xh);
    cudaGetSymbolAddress((void**)&xl, g_xl);
    cudaGetSymbolAddress((void**)&eh, g_eh);
    cudaGetSymbolAddress((void**)&el, g_el);
    cudaGetSymbolAddress((void**)&ath, g_ath);
    cudaGetSymbolAddress((void**)&atl, g_atl);
    cudaGetSymbolAddress((void**)&mh, g_mh);
    cudaGetSymbolAddress((void**)&ml, g_ml);

    __half *QH = fh,             *QL = fh + FH_PL;
    __half *KH = fh + 2 * FH_PL, *KL = fh + 3 * FH_PL;
    __half *VH = fh + 4 * FH_PL, *VL = fh + 5 * FH_PL;

    const int FSM = 6 * 128 * 72 * 2;
    cudaFuncSetAttribute(flash_attn, cudaFuncAttributeMaxDynamicSharedMemorySize, FSM);
    cudaFuncSetAttribute(pl_gemm, cudaFuncAttributeMaxDynamicSharedMemorySize, DSMEM);

    dim3 tb(32, 8);

    // weights -> planes [N][K]
    transpose_hilo<<<dim3(96, 32), tb>>>(c_attn_w, 3072, wh + WH_CA, wh + WH_CA + SZ_CA, 1024);
    transpose_hilo<<<dim3(32, 32), tb>>>(attn_proj_w, 1024, wh + WH_AP, wh + WH_AP + SZ_AP, 1024);
    transpose_hilo<<<dim3(32, 32), tb>>>(q_attn_w, 1024, wh + WH_QA, wh + WH_QA + SZ_QA, 1024);
    transpose_hilo<<<dim3(64, 32), tb>>>(x_kv_w, 2048, wh + WH_XKV, wh + WH_XKV + SZ_XKV, 1024);
    transpose_hilo<<<dim3(32, 32), tb>>>(x_proj_w, 1024, wh + WH_XP, wh + WH_XP + SZ_XP, 1024);
    transpose_hilo<<<dim3(128, 32), tb>>>(fc_w, 4096, wh + WH_FC, wh + WH_FC + SZ_FC, 1024);
    transpose_hilo<<<dim3(32, 128), tb>>>(mlp_proj_w, 1024, wh + WH_MP, wh + WH_MP + SZ_MP, 4096);
    split_plane<<<S_LEN, 256>>>(enc, eh, el);

    // ---- self attention ----
    ln_plane<<<S_LEN, 256>>>(hidden, ln1_g, ln1_b, xh, xl);
    pl_gemm<<<dim3(24, 16), 256, DSMEM>>>(xh, xl, 1024,
        wh + WH_CA, wh + WH_CA + SZ_CA, 1024,
        c_attn_b, nullptr, 0, qkv, nullptr, nullptr, 3072, 1024, 0);
    split_hilo<<<S_LEN, 256>>>(qkv, 3072, 0, QH, QL);
    split_hilo<<<S_LEN, 256>>>(qkv, 3072, 1024, KH, KL);
    split_hilo<<<S_LEN, 256>>>(qkv, 3072, 2048, VH, VL);
    flash_attn<<<dim3(16, NHEAD), 256, FSM>>>(QH, QL, KH, KL, VH, VL, nullptr, ath, atl, 0);
    pl_gemm<<<dim3(8, 16), 256, DSMEM>>>(ath, atl, 1024,
        wh + WH_AP, wh + WH_AP + SZ_AP, 1024,
        attn_proj_b, hidden, 1024, hid2, nullptr, nullptr, 1024, 1024, 0);

    // ---- cross attention ----
    ln_plane<<<S_LEN, 256>>>(hid2, lnx_g, lnx_b, xh, xl);
    pl_gemm<<<dim3(8, 16), 256, DSMEM>>>(xh, xl, 1024,
        wh + WH_QA, wh + WH_QA + SZ_QA, 1024,
        q_attn_b, nullptr, 0, qb, nullptr, nullptr, 1024, 1024, 0);
    pl_gemm<<<dim3(16, 16), 256, DSMEM>>>(eh, el, 1024,
        wh + WH_XKV, wh + WH_XKV + SZ_XKV, 1024,
        x_kv_b, nullptr, 0, kv, nullptr, nullptr, 2048, 1024, 0);
    split_hilo<<<S_LEN, 256>>>(qb, 1024, 0, QH, QL);
    split_hilo<<<S_LEN, 256>>>(kv, 2048, 0, KH, KL);
    split_hilo<<<S_LEN, 256>>>(kv, 2048, 1024, VH, VL);
    flash_attn<<<dim3(16, NHEAD), 256, FSM>>>(QH, QL, KH, KL, VH, VL, scorer, ath, atl, 1);
    pl_gemm<<<dim3(8, 16), 256, DSMEM>>>(ath, atl, 1024,
        wh + WH_XP, wh + WH_XP + SZ_XP, 1024,
        x_proj_b, hid2, 1024, hid3, nullptr, nullptr, 1024, 1024, 0);

    // ---- MLP ----
    ln_plane<<<S_LEN, 256>>>(hid3, ln2_g, ln2_b, xh, xl);
    pl_gemm<<<dim3(32, 16), 256, DSMEM>>>(xh, xl, 1024,
        wh + WH_FC, wh + WH_FC + SZ_FC, 1024,
        fc_b, nullptr, 0, nullptr, mh, ml, 4096, 1024, 1);
    pl_gemm<<<dim3(8, 16), 256, DSMEM>>>(mh, ml, 4096,
        wh + WH_MP, wh + WH_MP + SZ_MP, 4096,
        mlp_proj_b, hid3, 1024, out, nullptr, nullptr, 1024, 4096, 0);
}

// round 14
// speedup vs baseline: 1.8326x; 1.8326x over previous
#include <cuda_runtime.h>
#include <cuda_fp16.h>
#include <stdint.h>
#include <math.h>

#define S_LEN 2048
#define H_DIM 1024
#define NHEAD 16
#define HEADD 64
#define INNER_DIM 4096

// ---------------- scratch ----------------
__device__ float  g_qkv[S_LEN * 3 * H_DIM];
__device__ float  g_hid2[S_LEN * H_DIM];
__device__ float  g_hid3[S_LEN * H_DIM];
__device__ float  g_q[S_LEN * H_DIM];
__device__ float  g_kv[S_LEN * 2 * H_DIM];
__device__ __half g_wh[33554432];     // weight hi/lo planes
__device__ __half g_fh[12582912];     // per-head Q/K/V hi+lo planes
__device__ __half g_xh[2097152], g_xl[2097152];      // LN output planes
__device__ __half g_eh[2097152], g_el[2097152];      // encoder planes
__device__ __half g_ath[2097152], g_atl[2097152];    // attention output planes
__device__ __half g_mh[8388608],  g_ml[8388608];     // MLP inner planes

#define WH_CA  0
#define WH_AP  6291456
#define WH_QA  8388608
#define WH_XKV 10485760
#define WH_XP  14680064
#define WH_FC  16777216
#define WH_MP  25165824
#define SZ_CA  3145728
#define SZ_AP  1048576
#define SZ_QA  1048576
#define SZ_XKV 2097152
#define SZ_XP  1048576
#define SZ_FC  4194304
#define SZ_MP  4194304
#define FH_PL  2097152

#define SM_STRIDE 40   // 32 data + 8 pad halves

__device__ __forceinline__ float gelu_new(float x) {
    const float c = 0.7978845608028654f;
    return 0.5f * x * (1.0f + tanhf(c * (x + 0.044715f * x * x * x)));
}
__device__ __forceinline__ uint32_t smem_u32(const void* p) {
    uint32_t a;
    asm("{ .reg .u64 t; cvta.to.shared.u64 t, %1; cvt.u32.u64 %0, t; }" : "=r"(a) : "l"(p));
    return a;
}
__device__ __forceinline__ void mma_16816(float c[4], const uint32_t a[4], const uint32_t b[2]) {
    asm volatile("mma.sync.aligned.m16n8k16.row.col.f32.f16.f16.f32 "
        "{%0,%1,%2,%3}, {%4,%5,%6,%7}, {%8,%9}, {%0,%1,%2,%3};"
        : "+f"(c[0]), "+f"(c[1]), "+f"(c[2]), "+f"(c[3])
        : "r"(a[0]), "r"(a[1]), "r"(a[2]), "r"(a[3]), "r"(b[0]), "r"(b[1]));
}
__device__ __forceinline__ void ldm_x4(uint32_t r[4], uint32_t addr) {
    asm volatile("ldmatrix.sync.aligned.m8n8.x4.shared.b16 {%0,%1,%2,%3}, [%4];"
        : "=r"(r[0]), "=r"(r[1]), "=r"(r[2]), "=r"(r[3]) : "r"(addr));
}
__device__ __forceinline__ void ldm_x4_t(uint32_t r[4], uint32_t addr) {
    asm volatile("ldmatrix.sync.aligned.m8n8.x4.trans.shared.b16 {%0,%1,%2,%3}, [%4];"
        : "=r"(r[0]), "=r"(r[1]), "=r"(r[2]), "=r"(r[3]) : "r"(addr));
}

// ---- coalesced plane loaders: 128 rows x 32 halves per plane ----
__device__ __forceinline__ void ldg_pl(uint4 (&vh)[2], uint4 (&vl)[2],
                                       const __half* Ph, const __half* Pl,
                                       int ld, int row0, int k0, int t) {
    int row = t >> 1, seg = t & 1;
    const __half* ph = Ph + (long long)(row0 + row) * ld + k0 + seg * 16;
    const __half* pl = Pl + (long long)(row0 + row) * ld + k0 + seg * 16;
    vh[0] = ((const uint4*)ph)[0]; vh[1] = ((const uint4*)ph)[1];
    vl[0] = ((const uint4*)pl)[0]; vl[1] = ((const uint4*)pl)[1];
}
__device__ __forceinline__ void sts_pl(const uint4 (&vh)[2], const uint4 (&vl)[2],
                                       __half* hi, __half* lo, int t) {
    int row = t >> 1, seg = t & 1;
    __half* ph = hi + row * SM_STRIDE + seg * 16;
    __half* pl = lo + row * SM_STRIDE + seg * 16;
    ((uint4*)ph)[0] = vh[0]; ((uint4*)ph)[1] = vh[1];
    ((uint4*)pl)[0] = vl[0]; ((uint4*)pl)[1] = vl[1];
}

// one 32-wide K chunk: 3 combos (AhBh + AhBl + AlBh), 4x4 fragment grid
__device__ __forceinline__ void compute_chunk(float (&acc)[4][4][4],
    uint32_t aH, uint32_t aL, uint32_t bH, uint32_t bL)
{
#pragma unroll
    for (int kk = 0; kk < 32; kk += 16) {
        uint32_t a[4][4], bq[2][4];
#pragma unroll
        for (int i = 0; i < 4; i++) ldm_x4(a[i], aH + (i * 16 * SM_STRIDE + kk) * 2);
        ldm_x4(bq[0], bH + kk * 2);
        ldm_x4(bq[1], bH + (16 * SM_STRIDE + kk) * 2);
#pragma unroll
        for (int i = 0; i < 4; i++)
#pragma unroll
            for (int j = 0; j < 4; j++) {
                uint32_t bf[2] = { bq[j >> 1][j & 1], bq[j >> 1][2 + (j & 1)] };
                mma_16816(acc[i][j], a[i], bf);
            }
        {   // A-hi x B-lo
            uint32_t blq[2][4];
            ldm_x4(blq[0], bL + kk * 2);
            ldm_x4(blq[1], bL + (16 * SM_STRIDE + kk) * 2);
#pragma unroll
            for (int i = 0; i < 4; i++)
#pragma unroll
                for (int j = 0; j < 4; j++) {
                    uint32_t bf[2] = { blq[j >> 1][j & 1], blq[j >> 1][2 + (j & 1)] };
                    mma_16816(acc[i][j], a[i], bf);
                }
        }
        {   // A-lo x B-hi
            uint32_t al[4][4];
#pragma unroll
            for (int i = 0; i < 4; i++) ldm_x4(al[i], aL + (i * 16 * SM_STRIDE + kk) * 2);
#pragma unroll
            for (int i = 0; i < 4; i++)
#pragma unroll
                for (int j = 0; j < 4; j++) {
                    uint32_t bf[2] = { bq[j >> 1][j & 1], bq[j >> 1][2 + (j & 1)] };
                    mma_16816(acc[i][j], al[i], bf);
                }
        }
    }
}

// ================= dense plane x plane GEMM ================================
// C[M,N] = A[M,K] @ B^T. A,B as fp16 hi/lo planes ([M][K] / [N][K]).
// 128x128 tile, BK=32, register prefetch + single-stage smem (round-11 scheme).
__global__ void __launch_bounds__(256) pl_gemm(
    const __half* __restrict__ Ah, const __half* __restrict__ Al, int lda,
    const __half* __restrict__ Bh, const __half* __restrict__ Bl, int ldb,
    const float* __restrict__ bias, const float* __restrict__ res, int ldres,
    float* C, __half* Ch, __half* Cl, int ldc, int K, int act)
{
    constexpr int ASZ = 128 * SM_STRIDE;
    __shared__ __align__(16) __half As[2 * ASZ];
    __shared__ __align__(16) __half Bs[2 * ASZ];

    int t = threadIdx.x, w = t >> 5, lane = t & 31;
    int warpY = w & 1, warpX = w >> 1;
    int wm0 = warpY * 64, wn0 = warpX * 32;
    int m0 = blockIdx.y * 128, n0 = blockIdx.x * 128;

    int loff = ((lane & 7) + ((lane >> 3) & 1) * 8) * SM_STRIDE + (lane >> 4) * 8;
    uint32_t aHa = smem_u32(As) + (wm0 * SM_STRIDE + loff) * 2;
    uint32_t aLa = aHa + ASZ * 2;
    uint32_t bHa = smem_u32(Bs) + (wn0 * SM_STRIDE + loff) * 2;
    uint32_t bLa = bHa + ASZ * 2;

    float acc[4][4][4] = {};
    uint4 vah[2], val[2], vbh[2], vbl[2];

    ldg_pl(vah, val, Ah, Al, lda, m0, 0, t);
    ldg_pl(vbh, vbl, Bh, Bl, ldb, n0, 0, t);

    int nch = K >> 5;
    for (int c = 0; c < nch; c++) {
        sts_pl(vah, val, As, As + ASZ, t);
        sts_pl(vbh, vbl, Bs, Bs + ASZ, t);
        __syncthreads();
        if (c + 1 < nch) {
            int k0 = (c + 1) << 5;
            ldg_pl(vah, val, Ah, Al, lda, m0, k0, t);
            ldg_pl(vbh, vbl, Bh, Bl, ldb, n0, k0, t);
        }
        compute_chunk(acc, aHa, aLa, bHa, bLa);
        __syncthreads();
    }

    int rb = m0 + wm0 + (lane >> 2);
    int cb = n0 + wn0 + ((lane & 3) << 1);
#pragma unroll
    for (int i = 0; i < 4; i++) {
#pragma unroll
        for (int j = 0; j < 4; j++) {
            int cc = cb + j * 8;
            float b0 = bias ? bias[cc] : 0.f, b1 = bias ? bias[cc + 1] : 0.f;
#pragma unroll
            for (int h = 0; h < 2; h++) {
                int r = rb + i * 16 + h * 8;
                float v0 = acc[i][j][2 * h] + b0;
                float v1 = acc[i][j][2 * h + 1] + b1;
                if (act) { v0 = gelu_new(v0); v1 = gelu_new(v1); }
                if (Ch) {
                    __half h0 = __float2half_rn(v0), h1 = __float2half_rn(v1);
                    __half l0 = __float2half_rn(v0 - __half2float(h0));
                    __half l1 = __float2half_rn(v1 - __half2float(h1));
                    long long o = (long long)r * ldc + cc;
                    *(__half2*)&Ch[o] = __halves2half2(h0, h1);
                    *(__half2*)&Cl[o] = __halves2half2(l0, l1);
                } else {
                    if (res) {
                        const float* rp = res + (long long)r * ldres + cc;
                        v0 += rp[0]; v1 += rp[1];
                    }
                    *(float2*)&C[(long long)r * ldc + cc] = make_float2(v0, v1);
                }
            }
        }
    }
}

// ================= fused flash attention (outputs fp16 hi/lo planes) =======
__global__ void __launch_bounds__(256) flash_attn(
    const __half* __restrict__ QH, const __half* __restrict__ QL,
    const __half* __restrict__ KH, const __half* __restrict__ KL,
    const __half* __restrict__ VH, const __half* __restrict__ VL,
    const float* __restrict__ kbias,
    __half* __restrict__ OH, __half* __restrict__ OL, int mode)
{
    constexpr int ST = 72;
    constexpr int PL = 128 * ST;
    extern __shared__ __half sm[];
    __half* sQh = sm;
    __half* sKh = sm + 2 * PL;
    __half* sVh = sm + 4 * PL;

    int t = threadIdx.x, w = t >> 5, lane = t & 31;
    int qt = gridDim.x - 1 - blockIdx.x;
    int h = blockIdx.y;
    int m0 = qt * 128;
    size_t hb = (size_t)h * S_LEN * 64;

    {
        int row = t >> 1, seg = (t & 1) * 32;
        size_t g = hb + (size_t)(m0 + row) * 64 + seg;
        uint4* dh = (uint4*)(sQh + row * ST + seg);
        uint4* dl = (uint4*)(sQh + PL + row * ST + seg);
#pragma unroll
        for (int u = 0; u < 4; u++) {
            dh[u] = ((const uint4*)(QH + g))[u];
            dl[u] = ((const uint4*)(QL + g))[u];
        }
    }

    int wr = w * 16;
    int krow = (lane & 7) + ((lane >> 3) & 1) * 8;
    int chi = (lane >> 4) * 8;
    uint32_t aQh = smem_u32(sQh) + ((wr + krow) * ST + chi) * 2;
    uint32_t aK = smem_u32(sKh) + (krow * ST + chi) * 2;
    uint32_t aV = smem_u32(sVh) + (krow * ST + chi) * 2;

    float mrow0 = -1e30f, mrow1 = -1e30f, l0 = 0.f, l1 = 0.f;
    float o[8][4] = {};
    int r_lo = m0 + wr + (lane >> 2);
    int cbase = 2 * (lane & 3);

    int nkb = (mode == 0) ? (qt + 1) : min(16, qt + 2);
    for (int kb = 0; kb < nkb; kb++) {
        __syncthreads();
        {
            int row = t >> 1, seg = (t & 1) * 32;
            size_t g = hb + (size_t)(kb * 128 + row) * 64 + seg;
            uint4* d0 = (uint4*)(sKh + row * ST + seg);
            uint4* d1 = (uint4*)(sKh + PL + row * ST + seg);
            uint4* d2 = (uint4*)(sVh + row * ST + seg);
            uint4* d3 = (uint4*)(sVh + PL + row * ST + seg);
#pragma unroll
            for (int u = 0; u < 4; u++) {
                d0[u] = ((const uint4*)(KH + g))[u];
                d1[u] = ((const uint4*)(KL + g))[u];
                d2[u] = ((const uint4*)(VH + g))[u];
                d3[u] = ((const uint4*)(VL + g))[u];
            }
        }
        __syncthreads();

        float s[16][4] = {};
#pragma unroll
        for (int kk = 0; kk < 64; kk += 16) {
            uint32_t ah[4], al[4];
            ldm_x4(ah, aQh + kk * 2);
            ldm_x4(al, aQh + PL * 2 + kk * 2);
#pragma unroll
            for (int nb = 0; nb < 8; nb++) {
                uint32_t bh[4], bl[4];
                uint32_t off = (uint32_t)(nb * 16 * ST + kk) * 2;
                ldm_x4(bh, aK + off);
                ldm_x4(bl, aK + PL * 2 + off);
#pragma unroll
                for (int j = 0; j < 2; j++) {
                    uint32_t bfh[2] = { bh[j], bh[2 + j] };
                    uint32_t bfl[2] = { bl[j], bl[2 + j] };
                    mma_16816(s[nb * 2 + j], ah, bfh);
                    mma_16816(s[nb * 2 + j], ah, bfl);
                    mma_16816(s[nb * 2 + j], al, bfh);
                }
            }
        }

        int k0c = kb * 128;
        float mx0 = mrow0, mx1 = mrow1;
        int lim0 = (mode == 0) ? r_lo : r_lo + 2;
        int lim1 = lim0 + 8;
#pragma unroll
        for (int nf = 0; nf < 16; nf++) {
            int c0 = k0c + nf * 8 + cbase;
            float b0 = (mode == 1) ? kbias[c0] : 0.f;
            float b1 = (mode == 1) ? kbias[c0 + 1] : 0.f;
            s[nf][0] = (c0 <= lim0)     ? s[nf][0] * 0.125f + b0 : -1e30f;
            s[nf][1] = (c0 + 1 <= lim0) ? s[nf][1] * 0.125f + b1 : -1e30f;
            s[nf][2] = (c0 <= lim1)     ? s[nf][2] * 0.125f + b0 : -1e30f;
            s[nf][3] = (c0 + 1 <= lim1) ? s[nf][3] * 0.125f + b1 : -1e30f;
            mx0 = fmaxf(mx0, fmaxf(s[nf][0], s[nf][1]));
            mx1 = fmaxf(mx1, fmaxf(s[nf][2], s[nf][3]));
        }
        mx0 = fmaxf(mx0, __shfl_xor_sync(0xffffffffu, mx0, 1));
        mx0 = fmaxf(mx0, __shfl_xor_sync(0xffffffffu, mx0, 2));
        mx1 = fmaxf(mx1, __shfl_xor_sync(0xffffffffu, mx1, 1));
        mx1 = fmaxf(mx1, __shfl_xor_sync(0xffffffffu, mx1, 2));
        float corr0 = __expf(mrow0 - mx0), corr1 = __expf(mrow1 - mx1);
        mrow0 = mx0; mrow1 = mx1;

        float sum0 = 0.f, sum1 = 0.f;
        uint32_t p[16][2];
#pragma unroll
        for (int nf = 0; nf < 16; nf++) {
            float p0 = __expf(s[nf][0] - mx0), p1 = __expf(s[nf][1] - mx0);
            float p2 = __expf(s[nf][2] - mx1), p3 = __expf(s[nf][3] - mx1);
            sum0 += p0 + p1; sum1 += p2 + p3;
            __half2 h01 = __float22half2_rn(make_float2(p0, p1));
            __half2 h23 = __float22half2_rn(make_float2(p2, p3));
            p[nf][0] = *(uint32_t*)&h01;
            p[nf][1] = *(uint32_t*)&h23;
        }
        sum0 += __shfl_xor_sync(0xffffffffu, sum0, 1);
        sum0 += __shfl_xor_sync(0xffffffffu, sum0, 2);
        sum1 += __shfl_xor_sync(0xffffffffu, sum1, 1);
        sum1 += __shfl_xor_sync(0xffffffffu, sum1, 2);
        l0 = l0 * corr0 + sum0;
        l1 = l1 * corr1 + sum1;
#pragma unroll
        for (int df = 0; df < 8; df++) {
            o[df][0] *= corr0; o[df][1] *= corr0;
            o[df][2] *= corr1; o[df][3] *= corr1;
        }

#pragma unroll
        for (int kc = 0; kc < 8; kc++) {
            uint32_t a[4] = { p[2 * kc][0], p[2 * kc][1], p[2 * kc + 1][0], p[2 * kc + 1][1] };
#pragma unroll
            for (int dx = 0; dx < 4; dx++) {
                uint32_t bh[4], bl[4];
                uint32_t off = (uint32_t)(kc * 16 * ST + dx * 16) * 2;
                ldm_x4_t(bh, aV + off);
                ldm_x4_t(bl, aV + PL * 2 + off);
                uint32_t bf0[2] = { bh[0], bh[1] }, bf1[2] = { bh[2], bh[3] };
                uint32_t bg0[2] = { bl[0], bl[1] }, bg1[2] = { bl[2], bl[3] };
                mma_16816(o[dx * 2],     a, bf0);
                mma_16816(o[dx * 2 + 1], a, bf1);
                mma_16816(o[dx * 2],     a, bg0);
                mma_16816(o[dx * 2 + 1], a, bg1);
            }
        }
    }

    float inv0 = 1.f / l0, inv1 = 1.f / l1;
    int colb = h * 64 + cbase;
#pragma unroll
    for (int df = 0; df < 8; df++) {
        int cc = colb + df * 8;
        float v0 = o[df][0] * inv0, v1 = o[df][1] * inv0;
        float v2 = o[df][2] * inv1, v3 = o[df][3] * inv1;
        __half h0 = __float2half_rn(v0), h1 = __float2half_rn(v1);
        __half h2 = __float2half_rn(v2), h3 = __float2half_rn(v3);
        long long o0 = (long long)r_lo * H_DIM + cc;
        long long o1 = (long long)(r_lo + 8) * H_DIM + cc;
        *(__half2*)&OH[o0] = __halves2half2(h0, h1);
        *(__half2*)&OL[o0] = __halves2half2(__float2half_rn(v0 - __half2float(h0)),
                                            __float2half_rn(v1 - __half2float(h1)));
        *(__half2*)&OH[o1] = __halves2half2(h2, h3);
        *(__half2*)&OL[o1] = __halves2half2(__float2half_rn(v2 - __half2float(h2)),
                                            __float2half_rn(v3 - __half2float(h3)));
    }
}

// split fp32 [s][ld] cols coloff.. into per-head planes [h][s][64]
__global__ void split_hilo(const float* __restrict__ src, int ld, int coloff,
                           __half* __restrict__ hi, __half* __restrict__ lo)
{
    int s = blockIdx.x, t = threadIdx.x;
#pragma unroll
    for (int i = 0; i < 4; i++) {
        int c = t + i * 256;
        float v = src[(long long)s * ld + coloff + c];
        int hh = c >> 6, d = c & 63;
        __half hv = __float2half_rn(v);
        size_t o = ((size_t)hh * S_LEN + s) * 64 + d;
        hi[o] = hv;
        lo[o] = __float2half_rn(v - __half2float(hv));
    }
}

// split fp32 [s][1024] into row-major planes
__global__ void split_plane(const float* __restrict__ src,
                            __half* __restrict__ hi, __half* __restrict__ lo)
{
    int s = blockIdx.x, t = threadIdx.x;
#pragma unroll
    for (int i = 0; i < 4; i++) {
        int c = t + i * 256;
        float v = src[(long long)s * H_DIM + c];
        __half hv = __float2half_rn(v);
        long long o = (long long)s * H_DIM + c;
        hi[o] = hv;
        lo[o] = __float2half_rn(v - __half2float(hv));
    }
}

// LayerNorm emitting fp16 hi/lo planes
__global__ void ln_plane(const float* __restrict__ X, const float* __restrict__ g,
                         const float* __restrict__ b,
                         __half* __restrict__ YH, __half* __restrict__ YL)
{
    const float* x = X + (long long)blockIdx.x * H_DIM;
    long long yo = (long long)blockIdx.x * H_DIM;
    int tid = threadIdx.x;
    float v[4], s = 0.f, ss = 0.f;
#pragma unroll
    for (int i = 0; i < 4; i++) { v[i] = x[tid + i * 256]; s += v[i]; ss += v[i] * v[i]; }
    __shared__ float r1[256], r2[256];
    r1[tid] = s; r2[tid] = ss;
    __syncthreads();
#pragma unroll
    for (int st = 128; st >= 1; st >>= 1) {
        if (tid < st) { r1[tid] += r1[tid + st]; r2[tid] += r2[tid + st]; }
        __syncthreads();
    }
    float mean = r1[0] * (1.0f / H_DIM);
    float inv = rsqrtf(r2[0] * (1.0f / H_DIM) - mean * mean + 1e-5f);
#pragma unroll
    for (int i = 0; i < 4; i++) {
        int c = tid + i * 256;
        float y = (v[i] - mean) * inv * g[c] + b[c];
        __half h = __float2half_rn(y);
        YH[yo + c] = h;
        YL[yo + c] = __float2half_rn(y - __half2float(h));
    }
}

// transpose fp32 [r][c] -> fp16 hi/lo planes [c][r]  (weights)
__global__ void transpose_hilo(const float* __restrict__ in, int ldi,
                               __half* __restrict__ hi, __half* __restrict__ lo, int ldo)
{
    __shared__ float tbuf[32][33];
    int r0 = blockIdx.y * 32, c0 = blockIdx.x * 32;
    int tx = threadIdx.x, ty = threadIdx.y;
#pragma unroll
    for (int i = 0; i < 4; i++)
        tbuf[ty + i * 8][tx] = in[(long long)(r0 + ty + i * 8) * ldi + c0 + tx];
    __syncthreads();
#pragma unroll
    for (int i = 0; i < 4; i++) {
        float v = tbuf[tx][ty + i * 8];
        __half h = __float2half_rn(v);
        long long o = (long long)(c0 + ty + i * 8) * ldo + r0 + tx;
        hi[o] = h;
        lo[o] = __float2half_rn(v - __half2float(h));
    }
}

// ---------------------------------------------------------------------------
extern "C" void kernel_launch(void* const* d_in, const int* in_sizes, int n_in,
                              void* d_out, int out_size)
{
    const float* hidden = (const float*)d_in[0];
    const float* enc    = (const float*)d_in[1];
    const float* scorer = (const float*)d_in[2];
    const float* ln1_g = (const float*)d_in[3],  *ln1_b = (const float*)d_in[4];
    const float* c_attn_w = (const float*)d_in[5], *c_attn_b = (const float*)d_in[6];
    const float* attn_proj_w = (const float*)d_in[7], *attn_proj_b = (const float*)d_in[8];
    const float* lnx_g = (const float*)d_in[9],  *lnx_b = (const float*)d_in[10];
    const float* q_attn_w = (const float*)d_in[11], *q_attn_b = (const float*)d_in[12];
    const float* x_kv_w = (const float*)d_in[13], *x_kv_b = (const float*)d_in[14];
    const float* x_proj_w = (const float*)d_in[15], *x_proj_b = (const float*)d_in[16];
    const float* ln2_g = (const float*)d_in[17], *ln2_b = (const float*)d_in[18];
    const float* fc_w = (const float*)d_in[19], *fc_b = (const float*)d_in[20];
    const float* mlp_proj_w = (const float*)d_in[21], *mlp_proj_b = (const float*)d_in[22];
    float* out = (float*)d_out;

    float *qkv, *hid2, *hid3, *qb, *kv;
    __half *wh, *fh, *xh, *xl, *eh, *el, *ath, *atl, *mh, *ml;
    cudaGetSymbolAddress((void**)&qkv, g_qkv);
    cudaGetSymbolAddress((void**)&hid2, g_hid2);
    cudaGetSymbolAddress((void**)&hid3, g_hid3);
    cudaGetSymbolAddress((void**)&qb, g_q);
    cudaGetSymbolAddress((void**)&kv, g_kv);
    cudaGetSymbolAddress((void**)&wh, g_wh);
    cudaGetSymbolAddress((void**)&fh, g_fh);
    cudaGetSymbolAddress((void**)&xh, g_xh);
    cudaGetSymbolAddress((void**)&xl, g_xl);
    cudaGetSymbolAddress((void**)&eh, g_eh);
    cudaGetSymbolAddress((void**)&el, g_el);
    cudaGetSymbolAddress((void**)&ath, g_ath);
    cudaGetSymbolAddress((void**)&atl, g_atl);
    cudaGetSymbolAddress((void**)&mh, g_mh);
    cudaGetSymbolAddress((void**)&ml, g_ml);

    __half *QH = fh,             *QL = fh + FH_PL;
    __half *KH = fh + 2 * FH_PL, *KL = fh + 3 * FH_PL;
    __half *VH = fh + 4 * FH_PL, *VL = fh + 5 * FH_PL;

    const int FSM = 6 * 128 * 72 * 2;
    cudaFuncSetAttribute(flash_attn, cudaFuncAttributeMaxDynamicSharedMemorySize, FSM);

    dim3 tb(32, 8);

    // weights -> planes [N][K]
    transpose_hilo<<<dim3(96, 32), tb>>>(c_attn_w, 3072, wh + WH_CA, wh + WH_CA + SZ_CA, 1024);
    transpose_hilo<<<dim3(32, 32), tb>>>(attn_proj_w, 1024, wh + WH_AP, wh + WH_AP + SZ_AP, 1024);
    transpose_hilo<<<dim3(32, 32), tb>>>(q_attn_w, 1024, wh + WH_QA, wh + WH_QA + SZ_QA, 1024);
    transpose_hilo<<<dim3(64, 32), tb>>>(x_kv_w, 2048, wh + WH_XKV, wh + WH_XKV + SZ_XKV, 1024);
    transpose_hilo<<<dim3(32, 32), tb>>>(x_proj_w, 1024, wh + WH_XP, wh + WH_XP + SZ_XP, 1024);
    transpose_hilo<<<dim3(128, 32), tb>>>(fc_w, 4096, wh + WH_FC, wh + WH_FC + SZ_FC, 1024);
    transpose_hilo<<<dim3(32, 128), tb>>>(mlp_proj_w, 1024, wh + WH_MP, wh + WH_MP + SZ_MP, 4096);
    split_plane<<<S_LEN, 256>>>(enc, eh, el);

    // ---- self attention ----
    ln_plane<<<S_LEN, 256>>>(hidden, ln1_g, ln1_b, xh, xl);
    pl_gemm<<<dim3(24, 16), 256>>>(xh, xl, 1024,
        wh + WH_CA, wh + WH_CA + SZ_CA, 1024,
        c_attn_b, nullptr, 0, qkv, nullptr, nullptr, 3072, 1024, 0);
    split_hilo<<<S_LEN, 256>>>(qkv, 3072, 0, QH, QL);
    split_hilo<<<S_LEN, 256>>>(qkv, 3072, 1024, KH, KL);
    split_hilo<<<S_LEN, 256>>>(qkv, 3072, 2048, VH, VL);
    flash_attn<<<dim3(16, NHEAD), 256, FSM>>>(QH, QL, KH, KL, VH, VL, nullptr, ath, atl, 0);
    pl_gemm<<<dim3(8, 16), 256>>>(ath, atl, 1024,
        wh + WH_AP, wh + WH_AP + SZ_AP, 1024,
        attn_proj_b, hidden, 1024, hid2, nullptr, nullptr, 1024, 1024, 0);

    // ---- cross attention ----
    ln_plane<<<S_LEN, 256>>>(hid2, lnx_g, lnx_b, xh, xl);
    pl_gemm<<<dim3(8, 16), 256>>>(xh, xl, 1024,
        wh + WH_QA, wh + WH_QA + SZ_QA, 1024,
        q_attn_b, nullptr, 0, qb, nullptr, nullptr, 1024, 1024, 0);
    pl_gemm<<<dim3(16, 16), 256>>>(eh, el, 1024,
        wh + WH_XKV, wh + WH_XKV + SZ_XKV, 1024,
        x_kv_b, nullptr, 0, kv, nullptr, nullptr, 2048, 1024, 0);
    split_hilo<<<S_LEN, 256>>>(qb, 1024, 0, QH, QL);
    split_hilo<<<S_LEN, 256>>>(kv, 2048, 0, KH, KL);
    split_hilo<<<S_LEN, 256>>>(kv, 2048, 1024, VH, VL);
    flash_attn<<<dim3(16, NHEAD), 256, FSM>>>(QH, QL, KH, KL, VH, VL, scorer, ath, atl, 1);
    pl_gemm<<<dim3(8, 16), 256>>>(ath, atl, 1024,
        wh + WH_XP, wh + WH_XP + SZ_XP, 1024,
        x_proj_b, hid2, 1024, hid3, nullptr, nullptr, 1024, 1024, 0);

    // ---- MLP ----
    ln_plane<<<S_LEN, 256>>>(hid3, ln2_g, ln2_b, xh, xl);
    pl_gemm<<<dim3(32, 16), 256>>>(xh, xl, 1024,
        wh + WH_FC, wh + WH_FC + SZ_FC, 1024,
        fc_b, nullptr, 0, nullptr, mh, ml, 4096, 1024, 1);
    pl_gemm<<<dim3(8, 16), 256>>>(mh, ml, 4096,
        wh + WH_MP, wh + WH_MP + SZ_MP, 4096,
        mlp_proj_b, hid3, 1024, out, nullptr, nullptr, 1024, 4096, 0);
}

// round 15
// speedup vs baseline: 2.4033x; 1.3114x over previous
#include <cuda_runtime.h>
#include <cuda_fp16.h>
#include <stdint.h>
#include <math.h>

#define S_LEN 2048
#define H_DIM 1024
#define NHEAD 16
#define HEADD 64
#define INNER_DIM 4096

// ---------------- scratch ----------------
__device__ float  g_hid2[S_LEN * H_DIM];
__device__ float  g_hid3[S_LEN * H_DIM];
__device__ __half g_wh[33554432];     // weight hi/lo planes
__device__ __half g_fh[12582912];     // per-head Q/K/V hi+lo planes (6 x 2M)
__device__ __half g_xh[2097152];      // LN output plane (hi only)
__device__ __half g_eh[2097152];      // encoder plane
__device__ __half g_ath[2097152];     // attention output plane
__device__ __half g_mh[8388608];      // MLP inner plane

#define WH_CA  0
#define WH_AP  6291456
#define WH_QA  8388608
#define WH_XKV 10485760
#define WH_XP  14680064
#define WH_FC  16777216
#define WH_MP  25165824
#define SZ_CA  3145728
#define SZ_AP  1048576
#define SZ_QA  1048576
#define SZ_XKV 2097152
#define SZ_XP  1048576
#define SZ_FC  4194304
#define SZ_MP  4194304
#define FH_PL  2097152

#define SM_STRIDE 40   // 32 data + 8 pad halves

__device__ __forceinline__ float gelu_new(float x) {
    const float c = 0.7978845608028654f;
    return 0.5f * x * (1.0f + tanhf(c * (x + 0.044715f * x * x * x)));
}
__device__ __forceinline__ uint32_t smem_u32(const void* p) {
    uint32_t a;
    asm("{ .reg .u64 t; cvta.to.shared.u64 t, %1; cvt.u32.u64 %0, t; }" : "=r"(a) : "l"(p));
    return a;
}
__device__ __forceinline__ void mma_16816(float c[4], const uint32_t a[4], const uint32_t b[2]) {
    asm volatile("mma.sync.aligned.m16n8k16.row.col.f32.f16.f16.f32 "
        "{%0,%1,%2,%3}, {%4,%5,%6,%7}, {%8,%9}, {%0,%1,%2,%3};"
        : "+f"(c[0]), "+f"(c[1]), "+f"(c[2]), "+f"(c[3])
        : "r"(a[0]), "r"(a[1]), "r"(a[2]), "r"(a[3]), "r"(b[0]), "r"(b[1]));
}
__device__ __forceinline__ void ldm_x4(uint32_t r[4], uint32_t addr) {
    asm volatile("ldmatrix.sync.aligned.m8n8.x4.shared.b16 {%0,%1,%2,%3}, [%4];"
        : "=r"(r[0]), "=r"(r[1]), "=r"(r[2]), "=r"(r[3]) : "r"(addr));
}
__device__ __forceinline__ void ldm_x4_t(uint32_t r[4], uint32_t addr) {
    asm volatile("ldmatrix.sync.aligned.m8n8.x4.trans.shared.b16 {%0,%1,%2,%3}, [%4];"
        : "=r"(r[0]), "=r"(r[1]), "=r"(r[2]), "=r"(r[3]) : "r"(addr));
}

// ---- coalesced plane loaders (128 rows x 32 halves) ----
__device__ __forceinline__ void ldg_p1(uint4 (&v)[2], const __half* P, int ld,
                                       int row0, int k0, int t) {
    int row = t >> 1, seg = t & 1;
    const __half* p = P + (long long)(row0 + row) * ld + k0 + seg * 16;
    v[0] = ((const uint4*)p)[0]; v[1] = ((const uint4*)p)[1];
}
__device__ __forceinline__ void sts_p1(const uint4 (&v)[2], __half* s, int t) {
    int row = t >> 1, seg = t & 1;
    __half* p = s + row * SM_STRIDE + seg * 16;
    ((uint4*)p)[0] = v[0]; ((uint4*)p)[1] = v[1];
}

// one 32-wide K chunk: 2 combos (Ah*Bh + Ah*Bl), 4x4 fragment grid
__device__ __forceinline__ void compute_chunk2(float (&acc)[4][4][4],
    uint32_t aH, uint32_t bH, uint32_t bL)
{
#pragma unroll
    for (int kk = 0; kk < 32; kk += 16) {
        uint32_t a[4][4], bq[2][4], blq[2][4];
#pragma unroll
        for (int i = 0; i < 4; i++) ldm_x4(a[i], aH + (i * 16 * SM_STRIDE + kk) * 2);
        ldm_x4(bq[0], bH + kk * 2);
        ldm_x4(bq[1], bH + (16 * SM_STRIDE + kk) * 2);
#pragma unroll
        for (int i = 0; i < 4; i++)
#pragma unroll
            for (int j = 0; j < 4; j++) {
                uint32_t bf[2] = { bq[j >> 1][j & 1], bq[j >> 1][2 + (j & 1)] };
                mma_16816(acc[i][j], a[i], bf);
            }
        ldm_x4(blq[0], bL + kk * 2);
        ldm_x4(blq[1], bL + (16 * SM_STRIDE + kk) * 2);
#pragma unroll
        for (int i = 0; i < 4; i++)
#pragma unroll
            for (int j = 0; j < 4; j++) {
                uint32_t bf[2] = { blq[j >> 1][j & 1], blq[j >> 1][2 + (j & 1)] };
                mma_16816(acc[i][j], a[i], bf);
            }
    }
}

// ================= dense GEMM: A plain fp16, B hi/lo planes ================
// C[M,N] = A[M,K] @ B^T. Epilogue modes:
//   FHB != 0 : write per-head Q/K/V hi/lo planes (global col = colbase + cc)
//   Ch  != 0 : write fp16 hi plane
//   else     : write fp32 (+bias, +act, +res)
__global__ void __launch_bounds__(256) pl_gemm(
    const __half* __restrict__ Ah, int lda,
    const __half* __restrict__ Bh, const __half* __restrict__ Bl, int ldb,
    const float* __restrict__ bias, const float* __restrict__ res, int ldres,
    float* C, __half* Ch, __half* FHB, int colbase, int ldc, int K, int act)
{
    constexpr int ASZ = 128 * SM_STRIDE;
    __shared__ __align__(16) __half As[ASZ];
    __shared__ __align__(16) __half Bs[2 * ASZ];

    int t = threadIdx.x, w = t >> 5, lane = t & 31;
    int warpY = w & 1, warpX = w >> 1;
    int wm0 = warpY * 64, wn0 = warpX * 32;
    int m0 = blockIdx.y * 128, n0 = blockIdx.x * 128;

    int loff = ((lane & 7) + ((lane >> 3) & 1) * 8) * SM_STRIDE + (lane >> 4) * 8;
    uint32_t aHa = smem_u32(As) + (wm0 * SM_STRIDE + loff) * 2;
    uint32_t bHa = smem_u32(Bs) + (wn0 * SM_STRIDE + loff) * 2;
    uint32_t bLa = bHa + ASZ * 2;

    float acc[4][4][4] = {};
    uint4 va[2], vbh[2], vbl[2];

    ldg_p1(va, Ah, lda, m0, 0, t);
    ldg_p1(vbh, Bh, ldb, n0, 0, t);
    ldg_p1(vbl, Bl, ldb, n0, 0, t);

    int nch = K >> 5;
    for (int c = 0; c < nch; c++) {
        sts_p1(va, As, t);
        sts_p1(vbh, Bs, t);
        sts_p1(vbl, Bs + ASZ, t);
        __syncthreads();
        if (c + 1 < nch) {
            int k0 = (c + 1) << 5;
            ldg_p1(va, Ah, lda, m0, k0, t);
            ldg_p1(vbh, Bh, ldb, n0, k0, t);
            ldg_p1(vbl, Bl, ldb, n0, k0, t);
        }
        compute_chunk2(acc, aHa, bHa, bLa);
        __syncthreads();
    }

    int rb = m0 + wm0 + (lane >> 2);
    int cb = n0 + wn0 + ((lane & 3) << 1);
#pragma unroll
    for (int i = 0; i < 4; i++) {
#pragma unroll
        for (int j = 0; j < 4; j++) {
            int cc = cb + j * 8;
            float b0 = bias ? bias[cc] : 0.f, b1 = bias ? bias[cc + 1] : 0.f;
#pragma unroll
            for (int h = 0; h < 2; h++) {
                int r = rb + i * 16 + h * 8;
                float v0 = acc[i][j][2 * h] + b0;
                float v1 = acc[i][j][2 * h + 1] + b1;
                if (act) { v0 = gelu_new(v0); v1 = gelu_new(v1); }
                if (FHB) {
                    // per-head Q/K/V hi/lo planes
                    int gc = colbase + cc;
                    int seg = gc >> 10, c1 = gc & 1023;
                    int hh = c1 >> 6, d = c1 & 63;
                    size_t o = (size_t)(seg * 2) * FH_PL +
                               (((size_t)hh * S_LEN + r) * 64 + d);
                    __half h0 = __float2half_rn(v0), h1 = __float2half_rn(v1);
                    *(__half2*)&FHB[o] = __halves2half2(h0, h1);
                    *(__half2*)&FHB[o + FH_PL] =
                        __halves2half2(__float2half_rn(v0 - __half2float(h0)),
                                       __float2half_rn(v1 - __half2float(h1)));
                } else if (Ch) {
                    long long o = (long long)r * ldc + cc;
                    *(__half2*)&Ch[o] = __halves2half2(__float2half_rn(v0),
                                                       __float2half_rn(v1));
                } else {
                    if (res) {
                        const float* rp = res + (long long)r * ldres + cc;
                        v0 += rp[0]; v1 += rp[1];
                    }
                    *(float2*)&C[(long long)r * ldc + cc] = make_float2(v0, v1);
                }
            }
        }
    }
}

// ================= fused flash attention (outputs fp16 plane) ==============
__global__ void __launch_bounds__(256) flash_attn(
    const __half* __restrict__ QH, const __half* __restrict__ QL,
    const __half* __restrict__ KH, const __half* __restrict__ KL,
    const __half* __restrict__ VH, const __half* __restrict__ VL,
    const float* __restrict__ kbias, __half* __restrict__ OH, int mode)
{
    constexpr int ST = 72;
    constexpr int PL = 128 * ST;
    extern __shared__ __half sm[];
    __half* sQh = sm;
    __half* sKh = sm + 2 * PL;
    __half* sVh = sm + 4 * PL;

    int t = threadIdx.x, w = t >> 5, lane = t & 31;
    int qt = gridDim.x - 1 - blockIdx.x;
    int h = blockIdx.y;
    int m0 = qt * 128;
    size_t hb = (size_t)h * S_LEN * 64;

    {
        int row = t >> 1, seg = (t & 1) * 32;
        size_t g = hb + (size_t)(m0 + row) * 64 + seg;
        uint4* dh = (uint4*)(sQh + row * ST + seg);
        uint4* dl = (uint4*)(sQh + PL + row * ST + seg);
#pragma unroll
        for (int u = 0; u < 4; u++) {
            dh[u] = ((const uint4*)(QH + g))[u];
            dl[u] = ((const uint4*)(QL + g))[u];
        }
    }

    int wr = w * 16;
    int krow = (lane & 7) + ((lane >> 3) & 1) * 8;
    int chi = (lane >> 4) * 8;
    uint32_t aQh = smem_u32(sQh) + ((wr + krow) * ST + chi) * 2;
    uint32_t aK = smem_u32(sKh) + (krow * ST + chi) * 2;
    uint32_t aV = smem_u32(sVh) + (krow * ST + chi) * 2;

    float mrow0 = -1e30f, mrow1 = -1e30f, l0 = 0.f, l1 = 0.f;
    float o[8][4] = {};
    int r_lo = m0 + wr + (lane >> 2);
    int cbase = 2 * (lane & 3);

    int nkb = (mode == 0) ? (qt + 1) : min(16, qt + 2);
    for (int kb = 0; kb < nkb; kb++) {
        __syncthreads();
        {
            int row = t >> 1, seg = (t & 1) * 32;
            size_t g = hb + (size_t)(kb * 128 + row) * 64 + seg;
            uint4* d0 = (uint4*)(sKh + row * ST + seg);
            uint4* d1 = (uint4*)(sKh + PL + row * ST + seg);
            uint4* d2 = (uint4*)(sVh + row * ST + seg);
            uint4* d3 = (uint4*)(sVh + PL + row * ST + seg);
#pragma unroll
            for (int u = 0; u < 4; u++) {
                d0[u] = ((const uint4*)(KH + g))[u];
                d1[u] = ((const uint4*)(KL + g))[u];
                d2[u] = ((const uint4*)(VH + g))[u];
                d3[u] = ((const uint4*)(VL + g))[u];
            }
        }
        __syncthreads();

        float s[16][4] = {};
#pragma unroll
        for (int kk = 0; kk < 64; kk += 16) {
            uint32_t ah[4], al[4];
            ldm_x4(ah, aQh + kk * 2);
            ldm_x4(al, aQh + PL * 2 + kk * 2);
#pragma unroll
            for (int nb = 0; nb < 8; nb++) {
                uint32_t bh[4], bl[4];
                uint32_t off = (uint32_t)(nb * 16 * ST + kk) * 2;
                ldm_x4(bh, aK + off);
                ldm_x4(bl, aK + PL * 2 + off);
#pragma unroll
                for (int j = 0; j < 2; j++) {
                    uint32_t bfh[2] = { bh[j], bh[2 + j] };
                    uint32_t bfl[2] = { bl[j], bl[2 + j] };
                    mma_16816(s[nb * 2 + j], ah, bfh);
                    mma_16816(s[nb * 2 + j], ah, bfl);
                    mma_16816(s[nb * 2 + j], al, bfh);
                }
            }
        }

        int k0c = kb * 128;
        float mx0 = mrow0, mx1 = mrow1;
        int lim0 = (mode == 0) ? r_lo : r_lo + 2;
        int lim1 = lim0 + 8;
#pragma unroll
        for (int nf = 0; nf < 16; nf++) {
            int c0 = k0c + nf * 8 + cbase;
            float b0 = (mode == 1) ? kbias[c0] : 0.f;
            float b1 = (mode == 1) ? kbias[c0 + 1] : 0.f;
            s[nf][0] = (c0 <= lim0)     ? s[nf][0] * 0.125f + b0 : -1e30f;
            s[nf][1] = (c0 + 1 <= lim0) ? s[nf][1] * 0.125f + b1 : -1e30f;
            s[nf][2] = (c0 <= lim1)     ? s[nf][2] * 0.125f + b0 : -1e30f;
            s[nf][3] = (c0 + 1 <= lim1) ? s[nf][3] * 0.125f + b1 : -1e30f;
            mx0 = fmaxf(mx0, fmaxf(s[nf][0], s[nf][1]));
            mx1 = fmaxf(mx1, fmaxf(s[nf][2], s[nf][3]));
        }
        mx0 = fmaxf(mx0, __shfl_xor_sync(0xffffffffu, mx0, 1));
        mx0 = fmaxf(mx0, __shfl_xor_sync(0xffffffffu, mx0, 2));
        mx1 = fmaxf(mx1, __shfl_xor_sync(0xffffffffu, mx1, 1));
        mx1 = fmaxf(mx1, __shfl_xor_sync(0xffffffffu, mx1, 2));
        float corr0 = __expf(mrow0 - mx0), corr1 = __expf(mrow1 - mx1);
        mrow0 = mx0; mrow1 = mx1;

        float sum0 = 0.f, sum1 = 0.f;
        uint32_t p[16][2];
#pragma unroll
        for (int nf = 0; nf < 16; nf++) {
            float p0 = __expf(s[nf][0] - mx0), p1 = __expf(s[nf][1] - mx0);
            float p2 = __expf(s[nf][2] - mx1), p3 = __expf(s[nf][3] - mx1);
            sum0 += p0 + p1; sum1 += p2 + p3;
            __half2 h01 = __float22half2_rn(make_float2(p0, p1));
            __half2 h23 = __float22half2_rn(make_float2(p2, p3));
            p[nf][0] = *(uint32_t*)&h01;
            p[nf][1] = *(uint32_t*)&h23;
        }
        sum0 += __shfl_xor_sync(0xffffffffu, sum0, 1);
        sum0 += __shfl_xor_sync(0xffffffffu, sum0, 2);
        sum1 += __shfl_xor_sync(0xffffffffu, sum1, 1);
        sum1 += __shfl_xor_sync(0xffffffffu, sum1, 2);
        l0 = l0 * corr0 + sum0;
        l1 = l1 * corr1 + sum1;
#pragma unroll
        for (int df = 0; df < 8; df++) {
            o[df][0] *= corr0; o[df][1] *= corr0;
            o[df][2] *= corr1; o[df][3] *= corr1;
        }

#pragma unroll
        for (int kc = 0; kc < 8; kc++) {
            uint32_t a[4] = { p[2 * kc][0], p[2 * kc][1], p[2 * kc + 1][0], p[2 * kc + 1][1] };
#pragma unroll
            for (int dx = 0; dx < 4; dx++) {
                uint32_t bh[4], bl[4];
                uint32_t off = (uint32_t)(kc * 16 * ST + dx * 16) * 2;
                ldm_x4_t(bh, aV + off);
                ldm_x4_t(bl, aV + PL * 2 + off);
                uint32_t bf0[2] = { bh[0], bh[1] }, bf1[2] = { bh[2], bh[3] };
                uint32_t bg0[2] = { bl[0], bl[1] }, bg1[2] = { bl[2], bl[3] };
                mma_16816(o[dx * 2],     a, bf0);
                mma_16816(o[dx * 2 + 1], a, bf1);
                mma_16816(o[dx * 2],     a, bg0);
                mma_16816(o[dx * 2 + 1], a, bg1);
            }
        }
    }

    float inv0 = 1.f / l0, inv1 = 1.f / l1;
    int colb = h * 64 + cbase;
#pragma unroll
    for (int df = 0; df < 8; df++) {
        int cc = colb + df * 8;
        long long o0 = (long long)r_lo * H_DIM + cc;
        long long o1 = (long long)(r_lo + 8) * H_DIM + cc;
        *(__half2*)&OH[o0] = __halves2half2(__float2half_rn(o[df][0] * inv0),
                                            __float2half_rn(o[df][1] * inv0));
        *(__half2*)&OH[o1] = __halves2half2(__float2half_rn(o[df][2] * inv1),
                                            __float2half_rn(o[df][3] * inv1));
    }
}

// split fp32 [s][1024] into single fp16 plane
__global__ void split1(const float* __restrict__ src, __half* __restrict__ hi)
{
    int s = blockIdx.x, t = threadIdx.x;
#pragma unroll
    for (int i = 0; i < 4; i++) {
        int c = t + i * 256;
        hi[(long long)s * H_DIM + c] = __float2half_rn(src[(long long)s * H_DIM + c]);
    }
}

// LayerNorm emitting a single fp16 plane
__global__ void ln_h(const float* __restrict__ X, const float* __restrict__ g,
                     const float* __restrict__ b, __half* __restrict__ YH)
{
    const float* x = X + (long long)blockIdx.x * H_DIM;
    long long yo = (long long)blockIdx.x * H_DIM;
    int tid = threadIdx.x;
    float v[4], s = 0.f, ss = 0.f;
#pragma unroll
    for (int i = 0; i < 4; i++) { v[i] = x[tid + i * 256]; s += v[i]; ss += v[i] * v[i]; }
    __shared__ float r1[256], r2[256];
    r1[tid] = s; r2[tid] = ss;
    __syncthreads();
#pragma unroll
    for (int st = 128; st >= 1; st >>= 1) {
        if (tid < st) { r1[tid] += r1[tid + st]; r2[tid] += r2[tid + st]; }
        __syncthreads();
    }
    float mean = r1[0] * (1.0f / H_DIM);
    float inv = rsqrtf(r2[0] * (1.0f / H_DIM) - mean * mean + 1e-5f);
#pragma unroll
    for (int i = 0; i < 4; i++) {
        int c = tid + i * 256;
        float y = (v[i] - mean) * inv * g[c] + b[c];
        YH[yo + c] = __float2half_rn(y);
    }
}

// transpose fp32 [r][c] -> fp16 hi/lo planes [c][r]  (weights)
__global__ void transpose_hilo(const float* __restrict__ in, int ldi,
                               __half* __restrict__ hi, __half* __restrict__ lo, int ldo)
{
    __shared__ float tbuf[32][33];
    int r0 = blockIdx.y * 32, c0 = blockIdx.x * 32;
    int tx = threadIdx.x, ty = threadIdx.y;
#pragma unroll
    for (int i = 0; i < 4; i++)
        tbuf[ty + i * 8][tx] = in[(long long)(r0 + ty + i * 8) * ldi + c0 + tx];
    __syncthreads();
#pragma unroll
    for (int i = 0; i < 4; i++) {
        float v = tbuf[tx][ty + i * 8];
        __half h = __float2half_rn(v);
        long long o = (long long)(c0 + ty + i * 8) * ldo + r0 + tx;
        hi[o] = h;
        lo[o] = __float2half_rn(v - __half2float(h));
    }
}

// ---------------------------------------------------------------------------
extern "C" void kernel_launch(void* const* d_in, const int* in_sizes, int n_in,
                              void* d_out, int out_size)
{
    const float* hidden = (const float*)d_in[0];
    const float* enc    = (const float*)d_in[1];
    const float* scorer = (const float*)d_in[2];
    const float* ln1_g = (const float*)d_in[3],  *ln1_b = (const float*)d_in[4];
    const float* c_attn_w = (const float*)d_in[5], *c_attn_b = (const float*)d_in[6];
    const float* attn_proj_w = (const float*)d_in[7], *attn_proj_b = (const float*)d_in[8];
    const float* lnx_g = (const float*)d_in[9],  *lnx_b = (const float*)d_in[10];
    const float* q_attn_w = (const float*)d_in[11], *q_attn_b = (const float*)d_in[12];
    const float* x_kv_w = (const float*)d_in[13], *x_kv_b = (const float*)d_in[14];
    const float* x_proj_w = (const float*)d_in[15], *x_proj_b = (const float*)d_in[16];
    const float* ln2_g = (const float*)d_in[17], *ln2_b = (const float*)d_in[18];
    const float* fc_w = (const float*)d_in[19], *fc_b = (const float*)d_in[20];
    const float* mlp_proj_w = (const float*)d_in[21], *mlp_proj_b = (const float*)d_in[22];
    float* out = (float*)d_out;

    float *hid2, *hid3;
    __half *wh, *fh, *xh, *eh, *ath, *mh;
    cudaGetSymbolAddress((void**)&hid2, g_hid2);
    cudaGetSymbolAddress((void**)&hid3, g_hid3);
    cudaGetSymbolAddress((void**)&wh, g_wh);
    cudaGetSymbolAddress((void**)&fh, g_fh);
    cudaGetSymbolAddress((void**)&xh, g_xh);
    cudaGetSymbolAddress((void**)&eh, g_eh);
    cudaGetSymbolAddress((void**)&ath, g_ath);
    cudaGetSymbolAddress((void**)&mh, g_mh);

    __half *QH = fh,             *QL = fh + FH_PL;
    __half *KH = fh + 2 * FH_PL, *KL = fh + 3 * FH_PL;
    __half *VH = fh + 4 * FH_PL, *VL = fh + 5 * FH_PL;

    const int FSM = 6 * 128 * 72 * 2;
    cudaFuncSetAttribute(flash_attn, cudaFuncAttributeMaxDynamicSharedMemorySize, FSM);

    dim3 tb(32, 8);

    // weights -> hi/lo planes [N][K]
    transpose_hilo<<<dim3(96, 32), tb>>>(c_attn_w, 3072, wh + WH_CA, wh + WH_CA + SZ_CA, 1024);
    transpose_hilo<<<dim3(32, 32), tb>>>(attn_proj_w, 1024, wh + WH_AP, wh + WH_AP + SZ_AP, 1024);
    transpose_hilo<<<dim3(32, 32), tb>>>(q_attn_w, 1024, wh + WH_QA, wh + WH_QA + SZ_QA, 1024);
    transpose_hilo<<<dim3(64, 32), tb>>>(x_kv_w, 2048, wh + WH_XKV, wh + WH_XKV + SZ_XKV, 1024);
    transpose_hilo<<<dim3(32, 32), tb>>>(x_proj_w, 1024, wh + WH_XP, wh + WH_XP + SZ_XP, 1024);
    transpose_hilo<<<dim3(128, 32), tb>>>(fc_w, 4096, wh + WH_FC, wh + WH_FC + SZ_FC, 1024);
    transpose_hilo<<<dim3(32, 128), tb>>>(mlp_proj_w, 1024, wh + WH_MP, wh + WH_MP + SZ_MP, 4096);
    split1<<<S_LEN, 256>>>(enc, eh);

    // ---- self attention ----
    ln_h<<<S_LEN, 256>>>(hidden, ln1_g, ln1_b, xh);
    // qkv GEMM writes per-head Q/K/V hi/lo planes directly
    pl_gemm<<<dim3(24, 16), 256>>>(xh, 1024,
        wh + WH_CA, wh + WH_CA + SZ_CA, 1024,
        c_attn_b, nullptr, 0, nullptr, nullptr, fh, 0, 0, 1024, 0);
    flash_attn<<<dim3(16, NHEAD), 256, FSM>>>(QH, QL, KH, KL, VH, VL, nullptr, ath, 0);
    pl_gemm<<<dim3(8, 16), 256>>>(ath, 1024,
        wh + WH_AP, wh + WH_AP + SZ_AP, 1024,
        attn_proj_b, hidden, 1024, hid2, nullptr, nullptr, 0, 1024, 1024, 0);

    // ---- cross attention ----
    ln_h<<<S_LEN, 256>>>(hid2, lnx_g, lnx_b, xh);
    pl_gemm<<<dim3(8, 16), 256>>>(xh, 1024,
        wh + WH_QA, wh + WH_QA + SZ_QA, 1024,
        q_attn_b, nullptr, 0, nullptr, nullptr, fh, 0, 0, 1024, 0);      // Q planes
    pl_gemm<<<dim3(16, 16), 256>>>(eh, 1024,
        wh + WH_XKV, wh + WH_XKV + SZ_XKV, 1024,
        x_kv_b, nullptr, 0, nullptr, nullptr, fh, 1024, 0, 1024, 0);     // K,V planes
    flash_attn<<<dim3(16, NHEAD), 256, FSM>>>(QH, QL, KH, KL, VH, VL, scorer, ath, 1);
    pl_gemm<<<dim3(8, 16), 256>>>(ath, 1024,
        wh + WH_XP, wh + WH_XP + SZ_XP, 1024,
        x_proj_b, hid2, 1024, hid3, nullptr, nullptr, 0, 1024, 1024, 0);

    // ---- MLP ----
    ln_h<<<S_LEN, 256>>>(hid3, ln2_g, ln2_b, xh);
    pl_gemm<<<dim3(32, 16), 256>>>(xh, 1024,
        wh + WH_FC, wh + WH_FC + SZ_FC, 1024,
        fc_b, nullptr, 0, nullptr, mh, nullptr, 0, 4096, 1024, 1);
    pl_gemm<<<dim3(8, 16), 256>>>(mh, 4096,
        wh + WH_MP, wh + WH_MP + SZ_MP, 4096,
        mlp_proj_b, hid3, 1024, out, nullptr, nullptr, 0, 1024, 4096, 0);
}

// round 16
// speedup vs baseline: 2.7154x; 1.1299x over previous
#include <cuda_runtime.h>
#include <cuda_fp16.h>
#include <stdint.h>
#include <math.h>

#define S_LEN 2048
#define H_DIM 1024
#define NHEAD 16
#define HEADD 64
#define INNER_DIM 4096

// ---------------- scratch ----------------
__device__ float  g_hid2[S_LEN * H_DIM];
__device__ float  g_hid3[S_LEN * H_DIM];
__device__ __half g_wh[16777216];     // weight planes (fp16, single)
__device__ __half g_fh[12582912];     // per-head Q/K/V hi+lo planes (6 x 2M)
__device__ __half g_xh[2097152];      // LN output plane
__device__ __half g_eh[2097152];      // encoder plane
__device__ __half g_ath[2097152];     // attention output plane
__device__ __half g_mh[8388608];      // MLP inner plane

#define WH_CA  0
#define WH_AP  3145728
#define WH_QA  4194304
#define WH_XKV 5242880
#define WH_XP  7340032
#define WH_FC  8388608
#define WH_MP  12582912
#define FH_PL  2097152

#define SM_STRIDE 40   // 32 data + 8 pad halves

__device__ __forceinline__ float gelu_new(float x) {
    const float c = 0.7978845608028654f;
    return 0.5f * x * (1.0f + tanhf(c * (x + 0.044715f * x * x * x)));
}
__device__ __forceinline__ uint32_t smem_u32(const void* p) {
    uint32_t a;
    asm("{ .reg .u64 t; cvta.to.shared.u64 t, %1; cvt.u32.u64 %0, t; }" : "=r"(a) : "l"(p));
    return a;
}
__device__ __forceinline__ void mma_16816(float c[4], const uint32_t a[4], const uint32_t b[2]) {
    asm volatile("mma.sync.aligned.m16n8k16.row.col.f32.f16.f16.f32 "
        "{%0,%1,%2,%3}, {%4,%5,%6,%7}, {%8,%9}, {%0,%1,%2,%3};"
        : "+f"(c[0]), "+f"(c[1]), "+f"(c[2]), "+f"(c[3])
        : "r"(a[0]), "r"(a[1]), "r"(a[2]), "r"(a[3]), "r"(b[0]), "r"(b[1]));
}
__device__ __forceinline__ void ldm_x4(uint32_t r[4], uint32_t addr) {
    asm volatile("ldmatrix.sync.aligned.m8n8.x4.shared.b16 {%0,%1,%2,%3}, [%4];"
        : "=r"(r[0]), "=r"(r[1]), "=r"(r[2]), "=r"(r[3]) : "r"(addr));
}
__device__ __forceinline__ void ldm_x4_t(uint32_t r[4], uint32_t addr) {
    asm volatile("ldmatrix.sync.aligned.m8n8.x4.trans.shared.b16 {%0,%1,%2,%3}, [%4];"
        : "=r"(r[0]), "=r"(r[1]), "=r"(r[2]), "=r"(r[3]) : "r"(addr));
}

// ---- coalesced plane loaders (128 rows x 32 halves) ----
__device__ __forceinline__ void ldg_p1(uint4 (&v)[2], const __half* P, int ld,
                                       int row0, int k0, int t) {
    int row = t >> 1, seg = t & 1;
    const __half* p = P + (long long)(row0 + row) * ld + k0 + seg * 16;
    v[0] = ((const uint4*)p)[0]; v[1] = ((const uint4*)p)[1];
}
__device__ __forceinline__ void sts_p1(const uint4 (&v)[2], __half* s, int t) {
    int row = t >> 1, seg = t & 1;
    __half* p = s + row * SM_STRIDE + seg * 16;
    ((uint4*)p)[0] = v[0]; ((uint4*)p)[1] = v[1];
}

// one 32-wide K chunk: single combo (Ah*Bh), 4x4 fragment grid
__device__ __forceinline__ void compute_chunk1(float (&acc)[4][4][4],
    uint32_t aH, uint32_t bH)
{
#pragma unroll
    for (int kk = 0; kk < 32; kk += 16) {
        uint32_t a[4][4], bq[2][4];
#pragma unroll
        for (int i = 0; i < 4; i++) ldm_x4(a[i], aH + (i * 16 * SM_STRIDE + kk) * 2);
        ldm_x4(bq[0], bH + kk * 2);
        ldm_x4(bq[1], bH + (16 * SM_STRIDE + kk) * 2);
#pragma unroll
        for (int i = 0; i < 4; i++)
#pragma unroll
            for (int j = 0; j < 4; j++) {
                uint32_t bf[2] = { bq[j >> 1][j & 1], bq[j >> 1][2 + (j & 1)] };
                mma_16816(acc[i][j], a[i], bf);
            }
    }
}

// ================= dense GEMM: plain fp16 x plain fp16 =====================
// C[M,N] = A[M,K] @ B^T. Epilogue modes:
//   FHB != 0 : write per-head Q/K/V hi/lo planes (global col = colbase + cc)
//   Ch  != 0 : write fp16 plane
//   else     : write fp32 (+bias, +act, +res)
__global__ void __launch_bounds__(256) pl_gemm(
    const __half* __restrict__ Ah, int lda,
    const __half* __restrict__ Bh, int ldb,
    const float* __restrict__ bias, const float* __restrict__ res, int ldres,
    float* C, __half* Ch, __half* FHB, int colbase, int ldc, int K, int act)
{
    constexpr int ASZ = 128 * SM_STRIDE;
    __shared__ __align__(16) __half As[ASZ];
    __shared__ __align__(16) __half Bs[ASZ];

    int t = threadIdx.x, w = t >> 5, lane = t & 31;
    int warpY = w & 1, warpX = w >> 1;
    int wm0 = warpY * 64, wn0 = warpX * 32;
    int m0 = blockIdx.y * 128, n0 = blockIdx.x * 128;

    int loff = ((lane & 7) + ((lane >> 3) & 1) * 8) * SM_STRIDE + (lane >> 4) * 8;
    uint32_t aHa = smem_u32(As) + (wm0 * SM_STRIDE + loff) * 2;
    uint32_t bHa = smem_u32(Bs) + (wn0 * SM_STRIDE + loff) * 2;

    float acc[4][4][4] = {};
    uint4 va[2], vb[2];

    ldg_p1(va, Ah, lda, m0, 0, t);
    ldg_p1(vb, Bh, ldb, n0, 0, t);

    int nch = K >> 5;
    for (int c = 0; c < nch; c++) {
        sts_p1(va, As, t);
        sts_p1(vb, Bs, t);
        __syncthreads();
        if (c + 1 < nch) {
            int k0 = (c + 1) << 5;
            ldg_p1(va, Ah, lda, m0, k0, t);
            ldg_p1(vb, Bh, ldb, n0, k0, t);
        }
        compute_chunk1(acc, aHa, bHa);
        __syncthreads();
    }

    int rb = m0 + wm0 + (lane >> 2);
    int cb = n0 + wn0 + ((lane & 3) << 1);
#pragma unroll
    for (int i = 0; i < 4; i++) {
#pragma unroll
        for (int j = 0; j < 4; j++) {
            int cc = cb + j * 8;
            float b0 = bias ? bias[cc] : 0.f, b1 = bias ? bias[cc + 1] : 0.f;
#pragma unroll
            for (int h = 0; h < 2; h++) {
                int r = rb + i * 16 + h * 8;
                float v0 = acc[i][j][2 * h] + b0;
                float v1 = acc[i][j][2 * h + 1] + b1;
                if (act) { v0 = gelu_new(v0); v1 = gelu_new(v1); }
                if (FHB) {
                    int gc = colbase + cc;
                    int seg = gc >> 10, c1 = gc & 1023;
                    int hh = c1 >> 6, d = c1 & 63;
                    size_t o = (size_t)(seg * 2) * FH_PL +
                               (((size_t)hh * S_LEN + r) * 64 + d);
                    __half h0 = __float2half_rn(v0), h1 = __float2half_rn(v1);
                    *(__half2*)&FHB[o] = __halves2half2(h0, h1);
                    *(__half2*)&FHB[o + FH_PL] =
                        __halves2half2(__float2half_rn(v0 - __half2float(h0)),
                                       __float2half_rn(v1 - __half2float(h1)));
                } else if (Ch) {
                    long long o = (long long)r * ldc + cc;
                    *(__half2*)&Ch[o] = __halves2half2(__float2half_rn(v0),
                                                       __float2half_rn(v1));
                } else {
                    if (res) {
                        const float* rp = res + (long long)r * ldres + cc;
                        v0 += rp[0]; v1 += rp[1];
                    }
                    *(float2*)&C[(long long)r * ldc + cc] = make_float2(v0, v1);
                }
            }
        }
    }
}

// ================= fused flash attention (unchanged, hi/lo QKV) ============
__global__ void __launch_bounds__(256) flash_attn(
    const __half* __restrict__ QH, const __half* __restrict__ QL,
    const __half* __restrict__ KH, const __half* __restrict__ KL,
    const __half* __restrict__ VH, const __half* __restrict__ VL,
    const float* __restrict__ kbias, __half* __restrict__ OH, int mode)
{
    constexpr int ST = 72;
    constexpr int PL = 128 * ST;
    extern __shared__ __half sm[];
    __half* sQh = sm;
    __half* sKh = sm + 2 * PL;
    __half* sVh = sm + 4 * PL;

    int t = threadIdx.x, w = t >> 5, lane = t & 31;
    int qt = gridDim.x - 1 - blockIdx.x;
    int h = blockIdx.y;
    int m0 = qt * 128;
    size_t hb = (size_t)h * S_LEN * 64;

    {
        int row = t >> 1, seg = (t & 1) * 32;
        size_t g = hb + (size_t)(m0 + row) * 64 + seg;
        uint4* dh = (uint4*)(sQh + row * ST + seg);
        uint4* dl = (uint4*)(sQh + PL + row * ST + seg);
#pragma unroll
        for (int u = 0; u < 4; u++) {
            dh[u] = ((const uint4*)(QH + g))[u];
            dl[u] = ((const uint4*)(QL + g))[u];
        }
    }

    int wr = w * 16;
    int krow = (lane & 7) + ((lane >> 3) & 1) * 8;
    int chi = (lane >> 4) * 8;
    uint32_t aQh = smem_u32(sQh) + ((wr + krow) * ST + chi) * 2;
    uint32_t aK = smem_u32(sKh) + (krow * ST + chi) * 2;
    uint32_t aV = smem_u32(sVh) + (krow * ST + chi) * 2;

    float mrow0 = -1e30f, mrow1 = -1e30f, l0 = 0.f, l1 = 0.f;
    float o[8][4] = {};
    int r_lo = m0 + wr + (lane >> 2);
    int cbase = 2 * (lane & 3);

    int nkb = (mode == 0) ? (qt + 1) : min(16, qt + 2);
    for (int kb = 0; kb < nkb; kb++) {
        __syncthreads();
        {
            int row = t >> 1, seg = (t & 1) * 32;
            size_t g = hb + (size_t)(kb * 128 + row) * 64 + seg;
            uint4* d0 = (uint4*)(sKh + row * ST + seg);
            uint4* d1 = (uint4*)(sKh + PL + row * ST + seg);
            uint4* d2 = (uint4*)(sVh + row * ST + seg);
            uint4* d3 = (uint4*)(sVh + PL + row * ST + seg);
#pragma unroll
            for (int u = 0; u < 4; u++) {
                d0[u] = ((const uint4*)(KH + g))[u];
                d1[u] = ((const uint4*)(KL + g))[u];
                d2[u] = ((const uint4*)(VH + g))[u];
                d3[u] = ((const uint4*)(VL + g))[u];
            }
        }
        __syncthreads();

        float s[16][4] = {};
#pragma unroll
        for (int kk = 0; kk < 64; kk += 16) {
            uint32_t ah[4], al[4];
            ldm_x4(ah, aQh + kk * 2);
            ldm_x4(al, aQh + PL * 2 + kk * 2);
#pragma unroll
            for (int nb = 0; nb < 8; nb++) {
                uint32_t bh[4], bl[4];
                uint32_t off = (uint32_t)(nb * 16 * ST + kk) * 2;
                ldm_x4(bh, aK + off);
                ldm_x4(bl, aK + PL * 2 + off);
#pragma unroll
                for (int j = 0; j < 2; j++) {
                    uint32_t bfh[2] = { bh[j], bh[2 + j] };
                    uint32_t bfl[2] = { bl[j], bl[2 + j] };
                    mma_16816(s[nb * 2 + j], ah, bfh);
                    mma_16816(s[nb * 2 + j], ah, bfl);
                    mma_16816(s[nb * 2 + j], al, bfh);
                }
            }
        }

        int k0c = kb * 128;
        float mx0 = mrow0, mx1 = mrow1;
        int lim0 = (mode == 0) ? r_lo : r_lo + 2;
        int lim1 = lim0 + 8;
#pragma unroll
        for (int nf = 0; nf < 16; nf++) {
            int c0 = k0c + nf * 8 + cbase;
            float b0 = (mode == 1) ? kbias[c0] : 0.f;
            float b1 = (mode == 1) ? kbias[c0 + 1] : 0.f;
            s[nf][0] = (c0 <= lim0)     ? s[nf][0] * 0.125f + b0 : -1e30f;
            s[nf][1] = (c0 + 1 <= lim0) ? s[nf][1] * 0.125f + b1 : -1e30f;
            s[nf][2] = (c0 <= lim1)     ? s[nf][2] * 0.125f + b0 : -1e30f;
            s[nf][3] = (c0 + 1 <= lim1) ? s[nf][3] * 0.125f + b1 : -1e30f;
            mx0 = fmaxf(mx0, fmaxf(s[nf][0], s[nf][1]));
            mx1 = fmaxf(mx1, fmaxf(s[nf][2], s[nf][3]));
        }
        mx0 = fmaxf(mx0, __shfl_xor_sync(0xffffffffu, mx0, 1));
        mx0 = fmaxf(mx0, __shfl_xor_sync(0xffffffffu, mx0, 2));
        mx1 = fmaxf(mx1, __shfl_xor_sync(0xffffffffu, mx1, 1));
        mx1 = fmaxf(mx1, __shfl_xor_sync(0xffffffffu, mx1, 2));
        float corr0 = __expf(mrow0 - mx0), corr1 = __expf(mrow1 - mx1);
        mrow0 = mx0; mrow1 = mx1;

        float sum0 = 0.f, sum1 = 0.f;
        uint32_t p[16][2];
#pragma unroll
        for (int nf = 0; nf < 16; nf++) {
            float p0 = __expf(s[nf][0] - mx0), p1 = __expf(s[nf][1] - mx0);
            float p2 = __expf(s[nf][2] - mx1), p3 = __expf(s[nf][3] - mx1);
            sum0 += p0 + p1; sum1 += p2 + p3;
            __half2 h01 = __float22half2_rn(make_float2(p0, p1));
            __half2 h23 = __float22half2_rn(make_float2(p2, p3));
            p[nf][0] = *(uint32_t*)&h01;
            p[nf][1] = *(uint32_t*)&h23;
        }
        sum0 += __shfl_xor_sync(0xffffffffu, sum0, 1);
        sum0 += __shfl_xor_sync(0xffffffffu, sum0, 2);
        sum1 += __shfl_xor_sync(0xffffffffu, sum1, 1);
        sum1 += __shfl_xor_sync(0xffffffffu, sum1, 2);
        l0 = l0 * corr0 + sum0;
        l1 = l1 * corr1 + sum1;
#pragma unroll
        for (int df = 0; df < 8; df++) {
            o[df][0] *= corr0; o[df][1] *= corr0;
            o[df][2] *= corr1; o[df][3] *= corr1;
        }

#pragma unroll
        for (int kc = 0; kc < 8; kc++) {
            uint32_t a[4] = { p[2 * kc][0], p[2 * kc][1], p[2 * kc + 1][0], p[2 * kc + 1][1] };
#pragma unroll
            for (int dx = 0; dx < 4; dx++) {
                uint32_t bh[4], bl[4];
                uint32_t off = (uint32_t)(kc * 16 * ST + dx * 16) * 2;
                ldm_x4_t(bh, aV + off);
                ldm_x4_t(bl, aV + PL * 2 + off);
                uint32_t bf0[2] = { bh[0], bh[1] }, bf1[2] = { bh[2], bh[3] };
                uint32_t bg0[2] = { bl[0], bl[1] }, bg1[2] = { bl[2], bl[3] };
                mma_16816(o[dx * 2],     a, bf0);
                mma_16816(o[dx * 2 + 1], a, bf1);
                mma_16816(o[dx * 2],     a, bg0);
                mma_16816(o[dx * 2 + 1], a, bg1);
            }
        }
    }

    float inv0 = 1.f / l0, inv1 = 1.f / l1;
    int colb = h * 64 + cbase;
#pragma unroll
    for (int df = 0; df < 8; df++) {
        int cc = colb + df * 8;
        long long o0 = (long long)r_lo * H_DIM + cc;
        long long o1 = (long long)(r_lo + 8) * H_DIM + cc;
        *(__half2*)&OH[o0] = __halves2half2(__float2half_rn(o[df][0] * inv0),
                                            __float2half_rn(o[df][1] * inv0));
        *(__half2*)&OH[o1] = __halves2half2(__float2half_rn(o[df][2] * inv1),
                                            __float2half_rn(o[df][3] * inv1));
    }
}

// split fp32 [s][1024] into single fp16 plane
__global__ void split1(const float* __restrict__ src, __half* __restrict__ hi)
{
    int s = blockIdx.x, t = threadIdx.x;
#pragma unroll
    for (int i = 0; i < 4; i++) {
        int c = t + i * 256;
        hi[(long long)s * H_DIM + c] = __float2half_rn(src[(long long)s * H_DIM + c]);
    }
}

// LayerNorm emitting a single fp16 plane
__global__ void ln_h(const float* __restrict__ X, const float* __restrict__ g,
                     const float* __restrict__ b, __half* __restrict__ YH)
{
    const float* x = X + (long long)blockIdx.x * H_DIM;
    long long yo = (long long)blockIdx.x * H_DIM;
    int tid = threadIdx.x;
    float v[4], s = 0.f, ss = 0.f;
#pragma unroll
    for (int i = 0; i < 4; i++) { v[i] = x[tid + i * 256]; s += v[i]; ss += v[i] * v[i]; }
    __shared__ float r1[256], r2[256];
    r1[tid] = s; r2[tid] = ss;
    __syncthreads();
#pragma unroll
    for (int st = 128; st >= 1; st >>= 1) {
        if (tid < st) { r1[tid] += r1[tid + st]; r2[tid] += r2[tid + st]; }
        __syncthreads();
    }
    float mean = r1[0] * (1.0f / H_DIM);
    float inv = rsqrtf(r2[0] * (1.0f / H_DIM) - mean * mean + 1e-5f);
#pragma unroll
    for (int i = 0; i < 4; i++) {
        int c = tid + i * 256;
        float y = (v[i] - mean) * inv * g[c] + b[c];
        YH[yo + c] = __float2half_rn(y);
    }
}

// transpose fp32 [r][c] -> single fp16 plane [c][r]  (weights)
__global__ void transpose_h(const float* __restrict__ in, int ldi,
                            __half* __restrict__ hi, int ldo)
{
    __shared__ float tbuf[32][33];
    int r0 = blockIdx.y * 32, c0 = blockIdx.x * 32;
    int tx = threadIdx.x, ty = threadIdx.y;
#pragma unroll
    for (int i = 0; i < 4; i++)
        tbuf[ty + i * 8][tx] = in[(long long)(r0 + ty + i * 8) * ldi + c0 + tx];
    __syncthreads();
#pragma unroll
    for (int i = 0; i < 4; i++) {
        float v = tbuf[tx][ty + i * 8];
        hi[(long long)(c0 + ty + i * 8) * ldo + r0 + tx] = __float2half_rn(v);
    }
}

// ---------------------------------------------------------------------------
extern "C" void kernel_launch(void* const* d_in, const int* in_sizes, int n_in,
                              void* d_out, int out_size)
{
    const float* hidden = (const float*)d_in[0];
    const float* enc    = (const float*)d_in[1];
    const float* scorer = (const float*)d_in[2];
    const float* ln1_g = (const float*)d_in[3],  *ln1_b = (const float*)d_in[4];
    const float* c_attn_w = (const float*)d_in[5], *c_attn_b = (const float*)d_in[6];
    const float* attn_proj_w = (const float*)d_in[7], *attn_proj_b = (const float*)d_in[8];
    const float* lnx_g = (const float*)d_in[9],  *lnx_b = (const float*)d_in[10];
    const float* q_attn_w = (const float*)d_in[11], *q_attn_b = (const float*)d_in[12];
    const float* x_kv_w = (const float*)d_in[13], *x_kv_b = (const float*)d_in[14];
    const float* x_proj_w = (const float*)d_in[15], *x_proj_b = (const float*)d_in[16];
    const float* ln2_g = (const float*)d_in[17], *ln2_b = (const float*)d_in[18];
    const float* fc_w = (const float*)d_in[19], *fc_b = (const float*)d_in[20];
    const float* mlp_proj_w = (const float*)d_in[21], *mlp_proj_b = (const float*)d_in[22];
    float* out = (float*)d_out;

    float *hid2, *hid3;
    __half *wh, *fh, *xh, *eh, *ath, *mh;
    cudaGetSymbolAddress((void**)&hid2, g_hid2);
    cudaGetSymbolAddress((void**)&hid3, g_hid3);
    cudaGetSymbolAddress((void**)&wh, g_wh);
    cudaGetSymbolAddress((void**)&fh, g_fh);
    cudaGetSymbolAddress((void**)&xh, g_xh);
    cudaGetSymbolAddress((void**)&eh, g_eh);
    cudaGetSymbolAddress((void**)&ath, g_ath);
    cudaGetSymbolAddress((void**)&mh, g_mh);

    __half *QH = fh,             *QL = fh + FH_PL;
    __half *KH = fh + 2 * FH_PL, *KL = fh + 3 * FH_PL;
    __half *VH = fh + 4 * FH_PL, *VL = fh + 5 * FH_PL;

    const int FSM = 6 * 128 * 72 * 2;
    cudaFuncSetAttribute(flash_attn, cudaFuncAttributeMaxDynamicSharedMemorySize, FSM);

    dim3 tb(32, 8);

    // weights -> fp16 planes [N][K]
    transpose_h<<<dim3(96, 32), tb>>>(c_attn_w, 3072, wh + WH_CA, 1024);
    transpose_h<<<dim3(32, 32), tb>>>(attn_proj_w, 1024, wh + WH_AP, 1024);
    transpose_h<<<dim3(32, 32), tb>>>(q_attn_w, 1024, wh + WH_QA, 1024);
    transpose_h<<<dim3(64, 32), tb>>>(x_kv_w, 2048, wh + WH_XKV, 1024);
    transpose_h<<<dim3(32, 32), tb>>>(x_proj_w, 1024, wh + WH_XP, 1024);
    transpose_h<<<dim3(128, 32), tb>>>(fc_w, 4096, wh + WH_FC, 1024);
    transpose_h<<<dim3(32, 128), tb>>>(mlp_proj_w, 1024, wh + WH_MP, 4096);
    split1<<<S_LEN, 256>>>(enc, eh);

    // ---- self attention ----
    ln_h<<<S_LEN, 256>>>(hidden, ln1_g, ln1_b, xh);
    pl_gemm<<<dim3(24, 16), 256>>>(xh, 1024, wh + WH_CA, 1024,
        c_attn_b, nullptr, 0, nullptr, nullptr, fh, 0, 0, 1024, 0);
    flash_attn<<<dim3(16, NHEAD), 256, FSM>>>(QH, QL, KH, KL, VH, VL, nullptr, ath, 0);
    pl_gemm<<<dim3(8, 16), 256>>>(ath, 1024, wh + WH_AP, 1024,
        attn_proj_b, hidden, 1024, hid2, nullptr, nullptr, 0, 1024, 1024, 0);

    // ---- cross attention ----
    ln_h<<<S_LEN, 256>>>(hid2, lnx_g, lnx_b, xh);
    pl_gemm<<<dim3(8, 16), 256>>>(xh, 1024, wh + WH_QA, 1024,
        q_attn_b, nullptr, 0, nullptr, nullptr, fh, 0, 0, 1024, 0);      // Q planes
    pl_gemm<<<dim3(16, 16), 256>>>(eh, 1024, wh + WH_XKV, 1024,
        x_kv_b, nullptr, 0, nullptr, nullptr, fh, 1024, 0, 1024, 0);     // K,V planes
    flash_attn<<<dim3(16, NHEAD), 256, FSM>>>(QH, QL, KH, KL, VH, VL, scorer, ath, 1);
    pl_gemm<<<dim3(8, 16), 256>>>(ath, 1024, wh + WH_XP, 1024,
        x_proj_b, hid2, 1024, hid3, nullptr, nullptr, 0, 1024, 1024, 0);

    // ---- MLP ----
    ln_h<<<S_LEN, 256>>>(hid3, ln2_g, ln2_b, xh);
    pl_gemm<<<dim3(32, 16), 256>>>(xh, 1024, wh + WH_FC, 1024,
        fc_b, nullptr, 0, nullptr, mh, nullptr, 0, 4096, 1024, 1);
    pl_gemm<<<dim3(8, 16), 256>>>(mh, 4096, wh + WH_MP, 4096,
        mlp_proj_b, hid3, 1024, out, nullptr, nullptr, 0, 1024, 4096, 0);
}

// round 17
// speedup vs baseline: 3.2315x; 1.1901x over previous
#include <cuda_runtime.h>
#include <cuda_fp16.h>
#include <stdint.h>
#include <math.h>

#define S_LEN 2048
#define H_DIM 1024
#define NHEAD 16
#define HEADD 64
#define INNER_DIM 4096

// ---------------- scratch ----------------
__device__ float  g_hid2[S_LEN * H_DIM];
__device__ float  g_hid3[S_LEN * H_DIM];
__device__ __half g_wh[16777216];     // weight planes (fp16)
__device__ __half g_fh[12582912];     // per-head Q/K/V hi+lo planes (6 x 2M)
__device__ __half g_xh[2097152];      // LN output plane
__device__ __half g_eh[2097152];      // encoder plane
__device__ __half g_ath[2097152];     // attention output plane
__device__ __half g_mh[8388608];      // MLP inner plane

#define WH_CA  0
#define WH_AP  3145728
#define WH_QA  4194304
#define WH_XKV 5242880
#define WH_XP  7340032
#define WH_FC  8388608
#define WH_MP  12582912
#define FH_PL  2097152

#define SM_STRIDE 72   // 64 data + 8 pad halves (BK=64)

__device__ __forceinline__ float gelu_new(float x) {
    const float c = 0.7978845608028654f;
    return 0.5f * x * (1.0f + tanhf(c * (x + 0.044715f * x * x * x)));
}
__device__ __forceinline__ uint32_t smem_u32(const void* p) {
    uint32_t a;
    asm("{ .reg .u64 t; cvta.to.shared.u64 t, %1; cvt.u32.u64 %0, t; }" : "=r"(a) : "l"(p));
    return a;
}
__device__ __forceinline__ void mma_16816(float c[4], const uint32_t a[4], const uint32_t b[2]) {
    asm volatile("mma.sync.aligned.m16n8k16.row.col.f32.f16.f16.f32 "
        "{%0,%1,%2,%3}, {%4,%5,%6,%7}, {%8,%9}, {%0,%1,%2,%3};"
        : "+f"(c[0]), "+f"(c[1]), "+f"(c[2]), "+f"(c[3])
        : "r"(a[0]), "r"(a[1]), "r"(a[2]), "r"(a[3]), "r"(b[0]), "r"(b[1]));
}
__device__ __forceinline__ void ldm_x4(uint32_t r[4], uint32_t addr) {
    asm volatile("ldmatrix.sync.aligned.m8n8.x4.shared.b16 {%0,%1,%2,%3}, [%4];"
        : "=r"(r[0]), "=r"(r[1]), "=r"(r[2]), "=r"(r[3]) : "r"(addr));
}
__device__ __forceinline__ void ldm_x4_t(uint32_t r[4], uint32_t addr) {
    asm volatile("ldmatrix.sync.aligned.m8n8.x4.trans.shared.b16 {%0,%1,%2,%3}, [%4];"
        : "=r"(r[0]), "=r"(r[1]), "=r"(r[2]), "=r"(r[3]) : "r"(addr));
}

// ---- coalesced plane loaders (128 rows x 64 halves, 2 threads/row) ----
__device__ __forceinline__ void ldg_p1(uint4 (&v)[4], const __half* P, int ld,
                                       int row0, int k0, int t) {
    int row = t >> 1, seg = t & 1;
    const __half* p = P + (long long)(row0 + row) * ld + k0 + seg * 32;
#pragma unroll
    for (int u = 0; u < 4; u++) v[u] = ((const uint4*)p)[u];
}
__device__ __forceinline__ void sts_p1(const uint4 (&v)[4], __half* s, int t) {
    int row = t >> 1, seg = t & 1;
    __half* p = s + row * SM_STRIDE + seg * 32;
#pragma unroll
    for (int u = 0; u < 4; u++) ((uint4*)p)[u] = v[u];
}

// one 64-wide K chunk: single combo, 4x4 fragment grid
__device__ __forceinline__ void compute_chunk1(float (&acc)[4][4][4],
    uint32_t aH, uint32_t bH)
{
#pragma unroll
    for (int kk = 0; kk < 64; kk += 16) {
        uint32_t a[4][4], bq[2][4];
#pragma unroll
        for (int i = 0; i < 4; i++) ldm_x4(a[i], aH + (i * 16 * SM_STRIDE + kk) * 2);
        ldm_x4(bq[0], bH + kk * 2);
        ldm_x4(bq[1], bH + (16 * SM_STRIDE + kk) * 2);
#pragma unroll
        for (int i = 0; i < 4; i++)
#pragma unroll
            for (int j = 0; j < 4; j++) {
                uint32_t bf[2] = { bq[j >> 1][j & 1], bq[j >> 1][2 + (j & 1)] };
                mma_16816(acc[i][j], a[i], bf);
            }
    }
}

// ================= dense GEMM: plain fp16 x plain fp16, BK=64 ==============
__global__ void __launch_bounds__(256) pl_gemm(
    const __half* __restrict__ Ah, int lda,
    const __half* __restrict__ Bh, int ldb,
    const float* __restrict__ bias, const float* __restrict__ res, int ldres,
    float* C, __half* Ch, __half* FHB, int colbase, int ldc, int K, int act)
{
    constexpr int ASZ = 128 * SM_STRIDE;
    __shared__ __align__(16) __half As[ASZ];
    __shared__ __align__(16) __half Bs[ASZ];

    int t = threadIdx.x, w = t >> 5, lane = t & 31;
    int warpY = w & 1, warpX = w >> 1;
    int wm0 = warpY * 64, wn0 = warpX * 32;
    int m0 = blockIdx.y * 128, n0 = blockIdx.x * 128;

    int loff = ((lane & 7) + ((lane >> 3) & 1) * 8) * SM_STRIDE + (lane >> 4) * 8;
    uint32_t aHa = smem_u32(As) + (wm0 * SM_STRIDE + loff) * 2;
    uint32_t bHa = smem_u32(Bs) + (wn0 * SM_STRIDE + loff) * 2;

    float acc[4][4][4] = {};
    uint4 va[4], vb[4];

    ldg_p1(va, Ah, lda, m0, 0, t);
    ldg_p1(vb, Bh, ldb, n0, 0, t);

    int nch = K >> 6;
    for (int c = 0; c < nch; c++) {
        sts_p1(va, As, t);
        sts_p1(vb, Bs, t);
        __syncthreads();
        if (c + 1 < nch) {
            int k0 = (c + 1) << 6;
            ldg_p1(va, Ah, lda, m0, k0, t);
            ldg_p1(vb, Bh, ldb, n0, k0, t);
        }
        compute_chunk1(acc, aHa, bHa);
        __syncthreads();
    }

    int rb = m0 + wm0 + (lane >> 2);
    int cb = n0 + wn0 + ((lane & 3) << 1);
#pragma unroll
    for (int i = 0; i < 4; i++) {
#pragma unroll
        for (int j = 0; j < 4; j++) {
            int cc = cb + j * 8;
            float b0 = bias ? bias[cc] : 0.f, b1 = bias ? bias[cc + 1] : 0.f;
#pragma unroll
            for (int h = 0; h < 2; h++) {
                int r = rb + i * 16 + h * 8;
                float v0 = acc[i][j][2 * h] + b0;
                float v1 = acc[i][j][2 * h + 1] + b1;
                if (act) { v0 = gelu_new(v0); v1 = gelu_new(v1); }
                if (FHB) {
                    int gc = colbase + cc;
                    int seg = gc >> 10, c1 = gc & 1023;
                    int hh = c1 >> 6, d = c1 & 63;
                    size_t o = (size_t)(seg * 2) * FH_PL +
                               (((size_t)hh * S_LEN + r) * 64 + d);
                    __half h0 = __float2half_rn(v0), h1 = __float2half_rn(v1);
                    *(__half2*)&FHB[o] = __halves2half2(h0, h1);
                    *(__half2*)&FHB[o + FH_PL] =
                        __halves2half2(__float2half_rn(v0 - __half2float(h0)),
                                       __float2half_rn(v1 - __half2float(h1)));
                } else if (Ch) {
                    long long o = (long long)r * ldc + cc;
                    *(__half2*)&Ch[o] = __halves2half2(__float2half_rn(v0),
                                                       __float2half_rn(v1));
                } else {
                    if (res) {
                        const float* rp = res + (long long)r * ldres + cc;
                        v0 += rp[0]; v1 += rp[1];
                    }
                    *(float2*)&C[(long long)r * ldc + cc] = make_float2(v0, v1);
                }
            }
        }
    }
}

// ================= fused flash attention (Q/K hi/lo, V hi only) ============
__global__ void __launch_bounds__(256) flash_attn(
    const __half* __restrict__ QH, const __half* __restrict__ QL,
    const __half* __restrict__ KH, const __half* __restrict__ KL,
    const __half* __restrict__ VH,
    const float* __restrict__ kbias, __half* __restrict__ OH, int mode)
{
    constexpr int ST = 72;
    constexpr int PL = 128 * ST;
    extern __shared__ __half sm[];
    __half* sQh = sm;              // 2 planes (hi, lo)
    __half* sKh = sm + 2 * PL;     // 2 planes (hi, lo)
    __half* sVh = sm + 4 * PL;     // 1 plane (hi)

    int t = threadIdx.x, w = t >> 5, lane = t & 31;
    int qt = gridDim.x - 1 - blockIdx.x;
    int h = blockIdx.y;
    int m0 = qt * 128;
    size_t hb = (size_t)h * S_LEN * 64;

    {
        int row = t >> 1, seg = (t & 1) * 32;
        size_t g = hb + (size_t)(m0 + row) * 64 + seg;
        uint4* dh = (uint4*)(sQh + row * ST + seg);
        uint4* dl = (uint4*)(sQh + PL + row * ST + seg);
#pragma unroll
        for (int u = 0; u < 4; u++) {
            dh[u] = ((const uint4*)(QH + g))[u];
            dl[u] = ((const uint4*)(QL + g))[u];
        }
    }

    int wr = w * 16;
    int krow = (lane & 7) + ((lane >> 3) & 1) * 8;
    int chi = (lane >> 4) * 8;
    uint32_t aQh = smem_u32(sQh) + ((wr + krow) * ST + chi) * 2;
    uint32_t aK = smem_u32(sKh) + (krow * ST + chi) * 2;
    uint32_t aV = smem_u32(sVh) + (krow * ST + chi) * 2;

    float mrow0 = -1e30f, mrow1 = -1e30f, l0 = 0.f, l1 = 0.f;
    float o[8][4] = {};
    int r_lo = m0 + wr + (lane >> 2);
    int cbase = 2 * (lane & 3);

    int nkb = (mode == 0) ? (qt + 1) : min(16, qt + 2);
    for (int kb = 0; kb < nkb; kb++) {
        __syncthreads();
        {
            int row = t >> 1, seg = (t & 1) * 32;
            size_t g = hb + (size_t)(kb * 128 + row) * 64 + seg;
            uint4* d0 = (uint4*)(sKh + row * ST + seg);
            uint4* d1 = (uint4*)(sKh + PL + row * ST + seg);
            uint4* d2 = (uint4*)(sVh + row * ST + seg);
#pragma unroll
            for (int u = 0; u < 4; u++) {
                d0[u] = ((const uint4*)(KH + g))[u];
                d1[u] = ((const uint4*)(KL + g))[u];
                d2[u] = ((const uint4*)(VH + g))[u];
            }
        }
        __syncthreads();

        float s[16][4] = {};
#pragma unroll
        for (int kk = 0; kk < 64; kk += 16) {
            uint32_t ah[4], al[4];
            ldm_x4(ah, aQh + kk * 2);
            ldm_x4(al, aQh + PL * 2 + kk * 2);
#pragma unroll
            for (int nb = 0; nb < 8; nb++) {
                uint32_t bh[4], bl[4];
                uint32_t off = (uint32_t)(nb * 16 * ST + kk) * 2;
                ldm_x4(bh, aK + off);
                ldm_x4(bl, aK + PL * 2 + off);
#pragma unroll
                for (int j = 0; j < 2; j++) {
                    uint32_t bfh[2] = { bh[j], bh[2 + j] };
                    uint32_t bfl[2] = { bl[j], bl[2 + j] };
                    mma_16816(s[nb * 2 + j], ah, bfh);
                    mma_16816(s[nb * 2 + j], ah, bfl);
                    mma_16816(s[nb * 2 + j], al, bfh);
                }
            }
        }

        int k0c = kb * 128;
        float mx0 = mrow0, mx1 = mrow1;
        int lim0 = (mode == 0) ? r_lo : r_lo + 2;
        int lim1 = lim0 + 8;
#pragma unroll
        for (int nf = 0; nf < 16; nf++) {
            int c0 = k0c + nf * 8 + cbase;
            float b0 = (mode == 1) ? kbias[c0] : 0.f;
            float b1 = (mode == 1) ? kbias[c0 + 1] : 0.f;
            s[nf][0] = (c0 <= lim0)     ? s[nf][0] * 0.125f + b0 : -1e30f;
            s[nf][1] = (c0 + 1 <= lim0) ? s[nf][1] * 0.125f + b1 : -1e30f;
            s[nf][2] = (c0 <= lim1)     ? s[nf][2] * 0.125f + b0 : -1e30f;
            s[nf][3] = (c0 + 1 <= lim1) ? s[nf][3] * 0.125f + b1 : -1e30f;
            mx0 = fmaxf(mx0, fmaxf(s[nf][0], s[nf][1]));
            mx1 = fmaxf(mx1, fmaxf(s[nf][2], s[nf][3]));
        }
        mx0 = fmaxf(mx0, __shfl_xor_sync(0xffffffffu, mx0, 1));
        mx0 = fmaxf(mx0, __shfl_xor_sync(0xffffffffu, mx0, 2));
        mx1 = fmaxf(mx1, __shfl_xor_sync(0xffffffffu, mx1, 1));
        mx1 = fmaxf(mx1, __shfl_xor_sync(0xffffffffu, mx1, 2));
        float corr0 = __expf(mrow0 - mx0), corr1 = __expf(mrow1 - mx1);
        mrow0 = mx0; mrow1 = mx1;

        float sum0 = 0.f, sum1 = 0.f;
        uint32_t p[16][2];
#pragma unroll
        for (int nf = 0; nf < 16; nf++) {
            float p0 = __expf(s[nf][0] - mx0), p1 = __expf(s[nf][1] - mx0);
            float p2 = __expf(s[nf][2] - mx1), p3 = __expf(s[nf][3] - mx1);
            sum0 += p0 + p1; sum1 += p2 + p3;
            __half2 h01 = __float22half2_rn(make_float2(p0, p1));
            __half2 h23 = __float22half2_rn(make_float2(p2, p3));
            p[nf][0] = *(uint32_t*)&h01;
            p[nf][1] = *(uint32_t*)&h23;
        }
        sum0 += __shfl_xor_sync(0xffffffffu, sum0, 1);
        sum0 += __shfl_xor_sync(0xffffffffu, sum0, 2);
        sum1 += __shfl_xor_sync(0xffffffffu, sum1, 1);
        sum1 += __shfl_xor_sync(0xffffffffu, sum1, 2);
        l0 = l0 * corr0 + sum0;
        l1 = l1 * corr1 + sum1;
#pragma unroll
        for (int df = 0; df < 8; df++) {
            o[df][0] *= corr0; o[df][1] *= corr0;
            o[df][2] *= corr1; o[df][3] *= corr1;
        }

#pragma unroll
        for (int kc = 0; kc < 8; kc++) {
            uint32_t a[4] = { p[2 * kc][0], p[2 * kc][1], p[2 * kc + 1][0], p[2 * kc + 1][1] };
#pragma unroll
            for (int dx = 0; dx < 4; dx++) {
                uint32_t bh[4];
                uint32_t off = (uint32_t)(kc * 16 * ST + dx * 16) * 2;
                ldm_x4_t(bh, aV + off);
                uint32_t bf0[2] = { bh[0], bh[1] }, bf1[2] = { bh[2], bh[3] };
                mma_16816(o[dx * 2],     a, bf0);
                mma_16816(o[dx * 2 + 1], a, bf1);
            }
        }
    }

    float inv0 = 1.f / l0, inv1 = 1.f / l1;
    int colb = h * 64 + cbase;
#pragma unroll
    for (int df = 0; df < 8; df++) {
        int cc = colb + df * 8;
        long long o0 = (long long)r_lo * H_DIM + cc;
        long long o1 = (long long)(r_lo + 8) * H_DIM + cc;
        *(__half2*)&OH[o0] = __halves2half2(__float2half_rn(o[df][0] * inv0),
                                            __float2half_rn(o[df][1] * inv0));
        *(__half2*)&OH[o1] = __halves2half2(__float2half_rn(o[df][2] * inv1),
                                            __float2half_rn(o[df][3] * inv1));
    }
}

// split fp32 [s][1024] into single fp16 plane
__global__ void split1(const float* __restrict__ src, __half* __restrict__ hi)
{
    int s = blockIdx.x, t = threadIdx.x;
#pragma unroll
    for (int i = 0; i < 4; i++) {
        int c = t + i * 256;
        hi[(long long)s * H_DIM + c] = __float2half_rn(src[(long long)s * H_DIM + c]);
    }
}

// LayerNorm emitting a single fp16 plane
__global__ void ln_h(const float* __restrict__ X, const float* __restrict__ g,
                     const float* __restrict__ b, __half* __restrict__ YH)
{
    const float* x = X + (long long)blockIdx.x * H_DIM;
    long long yo = (long long)blockIdx.x * H_DIM;
    int tid = threadIdx.x;
    float v[4], s = 0.f, ss = 0.f;
#pragma unroll
    for (int i = 0; i < 4; i++) { v[i] = x[tid + i * 256]; s += v[i]; ss += v[i] * v[i]; }
    __shared__ float r1[256], r2[256];
    r1[tid] = s; r2[tid] = ss;
    __syncthreads();
#pragma unroll
    for (int st = 128; st >= 1; st >>= 1) {
        if (tid < st) { r1[tid] += r1[tid + st]; r2[tid] += r2[tid + st]; }
        __syncthreads();
    }
    float mean = r1[0] * (1.0f / H_DIM);
    float inv = rsqrtf(r2[0] * (1.0f / H_DIM) - mean * mean + 1e-5f);
#pragma unroll
    for (int i = 0; i < 4; i++) {
        int c = tid + i * 256;
        float y = (v[i] - mean) * inv * g[c] + b[c];
        YH[yo + c] = __float2half_rn(y);
    }
}

// transpose fp32 [r][c] -> single fp16 plane [c][r]  (weights)
__global__ void transpose_h(const float* __restrict__ in, int ldi,
                            __half* __restrict__ hi, int ldo)
{
    __shared__ float tbuf[32][33];
    int r0 = blockIdx.y * 32, c0 = blockIdx.x * 32;
    int tx = threadIdx.x, ty = threadIdx.y;
#pragma unroll
    for (int i = 0; i < 4; i++)
        tbuf[ty + i * 8][tx] = in[(long long)(r0 + ty + i * 8) * ldi + c0 + tx];
    __syncthreads();
#pragma unroll
    for (int i = 0; i < 4; i++) {
        float v = tbuf[tx][ty + i * 8];
        hi[(long long)(c0 + ty + i * 8) * ldo + r0 + tx] = __float2half_rn(v);
    }
}

// ---------------------------------------------------------------------------
extern "C" void kernel_launch(void* const* d_in, const int* in_sizes, int n_in,
                              void* d_out, int out_size)
{
    const float* hidden = (const float*)d_in[0];
    const float* enc    = (const float*)d_in[1];
    const float* scorer = (const float*)d_in[2];
    const float* ln1_g = (const float*)d_in[3],  *ln1_b = (const float*)d_in[4];
    const float* c_attn_w = (const float*)d_in[5], *c_attn_b = (const float*)d_in[6];
    const float* attn_proj_w = (const float*)d_in[7], *attn_proj_b = (const float*)d_in[8];
    const float* lnx_g = (const float*)d_in[9],  *lnx_b = (const float*)d_in[10];
    const float* q_attn_w = (const float*)d_in[11], *q_attn_b = (const float*)d_in[12];
    const float* x_kv_w = (const float*)d_in[13], *x_kv_b = (const float*)d_in[14];
    const float* x_proj_w = (const float*)d_in[15], *x_proj_b = (const float*)d_in[16];
    const float* ln2_g = (const float*)d_in[17], *ln2_b = (const float*)d_in[18];
    const float* fc_w = (const float*)d_in[19], *fc_b = (const float*)d_in[20];
    const float* mlp_proj_w = (const float*)d_in[21], *mlp_proj_b = (const float*)d_in[22];
    float* out = (float*)d_out;

    float *hid2, *hid3;
    __half *wh, *fh, *xh, *eh, *ath, *mh;
    cudaGetSymbolAddress((void**)&hid2, g_hid2);
    cudaGetSymbolAddress((void**)&hid3, g_hid3);
    cudaGetSymbolAddress((void**)&wh, g_wh);
    cudaGetSymbolAddress((void**)&fh, g_fh);
    cudaGetSymbolAddress((void**)&xh, g_xh);
    cudaGetSymbolAddress((void**)&eh, g_eh);
    cudaGetSymbolAddress((void**)&ath, g_ath);
    cudaGetSymbolAddress((void**)&mh, g_mh);

    __half *QH = fh,             *QL = fh + FH_PL;
    __half *KH = fh + 2 * FH_PL, *KL = fh + 3 * FH_PL;
    __half *VH = fh + 4 * FH_PL;

    const int FSM = 5 * 128 * 72 * 2;   // 92160 bytes
    cudaFuncSetAttribute(flash_attn, cudaFuncAttributeMaxDynamicSharedMemorySize, FSM);

    dim3 tb(32, 8);

    // weights -> fp16 planes [N][K]
    transpose_h<<<dim3(96, 32), tb>>>(c_attn_w, 3072, wh + WH_CA, 1024);
    transpose_h<<<dim3(32, 32), tb>>>(attn_proj_w, 1024, wh + WH_AP, 1024);
    transpose_h<<<dim3(32, 32), tb>>>(q_attn_w, 1024, wh + WH_QA, 1024);
    transpose_h<<<dim3(64, 32), tb>>>(x_kv_w, 2048, wh + WH_XKV, 1024);
    transpose_h<<<dim3(32, 32), tb>>>(x_proj_w, 1024, wh + WH_XP, 1024);
    transpose_h<<<dim3(128, 32), tb>>>(fc_w, 4096, wh + WH_FC, 1024);
    transpose_h<<<dim3(32, 128), tb>>>(mlp_proj_w, 1024, wh + WH_MP, 4096);
    split1<<<S_LEN, 256>>>(enc, eh);

    // ---- self attention ----
    ln_h<<<S_LEN, 256>>>(hidden, ln1_g, ln1_b, xh);
    pl_gemm<<<dim3(24, 16), 256>>>(xh, 1024, wh + WH_CA, 1024,
        c_attn_b, nullptr, 0, nullptr, nullptr, fh, 0, 0, 1024, 0);
    flash_attn<<<dim3(16, NHEAD), 256, FSM>>>(QH, QL, KH, KL, VH, nullptr, ath, 0);
    pl_gemm<<<dim3(8, 16), 256>>>(ath, 1024, wh + WH_AP, 1024,
        attn_proj_b, hidden, 1024, hid2, nullptr, nullptr, 0, 1024, 1024, 0);

    // ---- cross attention ----
    ln_h<<<S_LEN, 256>>>(hid2, lnx_g, lnx_b, xh);
    pl_gemm<<<dim3(8, 16), 256>>>(xh, 1024, wh + WH_QA, 1024,
        q_attn_b, nullptr, 0, nullptr, nullptr, fh, 0, 0, 1024, 0);      // Q planes
    pl_gemm<<<dim3(16, 16), 256>>>(eh, 1024, wh + WH_XKV, 1024,
        x_kv_b, nullptr, 0, nullptr, nullptr, fh, 1024, 0, 1024, 0);     // K,V planes
    flash_attn<<<dim3(16, NHEAD), 256, FSM>>>(QH, QL, KH, KL, VH, scorer, ath, 1);
    pl_gemm<<<dim3(8, 16), 256>>>(ath, 1024, wh + WH_XP, 1024,
        x_proj_b, hid2, 1024, hid3, nullptr, nullptr, 0, 1024, 1024, 0);

    // ---- MLP ----
    ln_h<<<S_LEN, 256>>>(hid3, ln2_g, ln2_b, xh);
    pl_gemm<<<dim3(32, 16), 256>>>(xh, 1024, wh + WH_FC, 1024,
        fc_b, nullptr, 0, nullptr, mh, nullptr, 0, 4096, 1024, 1);
    pl_gemm<<<dim3(8, 16), 256>>>(mh, 4096, wh + WH_MP, 4096,
        mlp_proj_b, hid3, 1024, out, nullptr, nullptr, 0, 1024, 4096, 0);
}